// round 4
// baseline (speedup 1.0000x reference)
#include <cuda_runtime.h>
#include <cstdint>
#include <cstddef>

#define BB   64
#define TT   256
#define DD   1024
#define HH   1024
#define G4   4096
#define NB   128

// ---------------- device scratch ----------------
__device__ float g_G0p[(size_t)TT * NB * 64 * 32];  // [t][bn][row64][gate8*4]
__device__ float g_Wx0c[DD * G4];
__device__ float g_Wh0p[HH * G4];   // packed [bn][kseg32][col32][kin32]
__device__ float g_Wx1p[HH * G4];
__device__ float g_Wh1p[HH * G4];
__device__ float g_b1p[NB * 32];
__device__ float g_h0r[2][BB * HH];
__device__ float g_h1r[2][BB * HH];
__device__ float g_h1e[BB * HH];
__device__ unsigned g_bar;

// ---------------- smem layout (bytes) ----------------
// stage: A = 4 groups x 64 rows x 36 floats = 36864 B
//        B = 2 sets x 4 groups x 32 cols x 36 floats = 36864 B   -> 73728 B
// 3 stages = 221184 ; G0 = 8192 ; total 229376
#define STAGE_B   73728
#define ST_A(s,g)        ((s)*STAGE_B + (g)*9216)
#define ST_B(s,set,g)    ((s)*STAGE_B + 36864 + ((set)*4+(g))*4608)
#define G0_OFF    221184
#define SMEM_BYTES 229376
// reduction buffer aliases stage 0..: [wk*2+layer][64 rows][36] floats

// ---------------- helpers ----------------
__device__ __forceinline__ uint32_t f2tf(float x) {
    uint32_t r; asm("cvt.rna.tf32.f32 %0, %1;" : "=r"(r) : "f"(x)); return r;
}
__device__ __forceinline__ void mma8(float* d, const uint32_t* a, const uint32_t* b) {
    asm volatile(
        "mma.sync.aligned.m16n8k8.row.col.f32.tf32.tf32.f32 "
        "{%0,%1,%2,%3}, {%4,%5,%6,%7}, {%8,%9}, {%0,%1,%2,%3};"
        : "+f"(d[0]), "+f"(d[1]), "+f"(d[2]), "+f"(d[3])
        : "r"(a[0]), "r"(a[1]), "r"(a[2]), "r"(a[3]), "r"(b[0]), "r"(b[1]));
}
__device__ __forceinline__ void cp16(uint32_t s, const void* g) {
    asm volatile("cp.async.cg.shared.global [%0], [%1], 16;" :: "r"(s), "l"(g));
}
#define CP_COMMIT() asm volatile("cp.async.commit_group;")
#define CP_WAIT1()  asm volatile("cp.async.wait_group 1;")
#define CP_WAIT0()  asm volatile("cp.async.wait_group 0;")

__device__ __forceinline__ float sigf(float x)   { return 1.f / (1.f + __expf(-x)); }
__device__ __forceinline__ float tanhf_(float x) { return 2.f / (1.f + __expf(-2.f * x)) - 1.f; }

// ---------------- convert + pack ----------------
__global__ void convert_pack_kernel(const float* __restrict__ Wx0, const float* __restrict__ Wh0,
                                    const float* __restrict__ Wx1, const float* __restrict__ Wh1,
                                    const float* __restrict__ b1) {
    const int n1 = 1 << 22;
    const int stride = gridDim.x * blockDim.x;
    for (int idx = blockIdx.x * blockDim.x + threadIdx.x; idx < 4 * n1; idx += stride) {
        int w = idx >> 22;
        int d = idx & (n1 - 1);
        if (w == 0) {
            g_Wx0c[d] = __uint_as_float(f2tf(Wx0[d]));
        } else {
            int kin = d & 31, col = (d >> 5) & 31, kseg = (d >> 10) & 31, bn = d >> 15;
            int gate = col >> 3, cw = col & 7;
            int src = (kseg * 32 + kin) * G4 + gate * HH + bn * 8 + cw;
            float v = (w == 1) ? Wh0[src] : (w == 2) ? Wx1[src] : Wh1[src];
            float* dst = (w == 1) ? g_Wh0p : (w == 2) ? g_Wx1p : g_Wh1p;
            dst[d] = __uint_as_float(f2tf(v));
        }
    }
    for (int i = blockIdx.x * blockDim.x + threadIdx.x; i < NB * 32; i += stride) {
        int bn = i >> 5, c = i & 31, gate = c >> 3, cw = c & 7;
        g_b1p[i] = b1[gate * HH + bn * 8 + cw];
    }
}

__global__ void init_kernel() {
    int i = blockIdx.x * blockDim.x + threadIdx.x;
    if (i < BB * HH) {
        g_h0r[0][i] = 0.f; g_h0r[1][i] = 0.f;
        g_h1r[0][i] = 0.f; g_h1r[1][i] = 0.f;
    }
    if (i == 0) g_bar = 0u;
}

// ---------------- precompute G0 = X @ Wx0 + b0 (packed) ----------------
__global__ void __launch_bounds__(256) xgemm_kernel(const float* __restrict__ x,
                                                    const float* __restrict__ b0) {
    __shared__ uint32_t sA[128][17];
    __shared__ float    sB[16][64];
    const int tid  = threadIdx.x;
    const int lane = tid & 31;
    const int warp = tid >> 5;
    const int warpM = warp & 1;
    const int warpN = warp >> 1;
    const int bm = blockIdx.y * 128;
    const int bn = blockIdx.x * 64;

    float acc[4][2][4];
#pragma unroll
    for (int i = 0; i < 4; i++)
#pragma unroll
        for (int j = 0; j < 2; j++)
#pragma unroll
            for (int p = 0; p < 4; p++) acc[i][j][p] = 0.f;

    const int arow = tid >> 1;
    const int acb  = (tid & 1) * 8;
    const int brow = tid >> 4;
    const int bcol = (tid & 15) * 4;

    for (int k0 = 0; k0 < DD; k0 += 16) {
        {
            const float* s = x + (size_t)(bm + arow) * DD + k0 + acb;
            float4 v0 = *(const float4*)s;
            float4 v1 = *(const float4*)(s + 4);
            sA[arow][acb + 0] = f2tf(v0.x); sA[arow][acb + 1] = f2tf(v0.y);
            sA[arow][acb + 2] = f2tf(v0.z); sA[arow][acb + 3] = f2tf(v0.w);
            sA[arow][acb + 4] = f2tf(v1.x); sA[arow][acb + 5] = f2tf(v1.y);
            sA[arow][acb + 6] = f2tf(v1.z); sA[arow][acb + 7] = f2tf(v1.w);
        }
        *(float4*)&sB[brow][bcol] =
            *(const float4*)(g_Wx0c + (size_t)(k0 + brow) * G4 + bn + bcol);
        __syncthreads();
#pragma unroll
        for (int ks = 0; ks < 2; ks++) {
            uint32_t a[4][4];
            const int kb = ks * 8 + (lane & 3);
#pragma unroll
            for (int mt = 0; mt < 4; mt++) {
                const int r = warpM * 64 + mt * 16 + (lane >> 2);
                a[mt][0] = sA[r][kb];     a[mt][1] = sA[r + 8][kb];
                a[mt][2] = sA[r][kb + 4]; a[mt][3] = sA[r + 8][kb + 4];
            }
#pragma unroll
            for (int nt = 0; nt < 2; nt++) {
                uint32_t b[2];
                const int c = warpN * 16 + nt * 8 + (lane >> 2);
                b[0] = __float_as_uint(sB[kb][c]);
                b[1] = __float_as_uint(sB[kb + 4][c]);
#pragma unroll
                for (int mt = 0; mt < 4; mt++) mma8(acc[mt][nt], a[mt], b);
            }
        }
        __syncthreads();
    }
#pragma unroll
    for (int mt = 0; mt < 4; mt++)
#pragma unroll
        for (int nt = 0; nt < 2; nt++)
#pragma unroll
            for (int p = 0; p < 4; p++) {
                int row = bm + warpM * 64 + mt * 16 + (lane >> 2) + ((p & 2) ? 8 : 0);
                int col = bn + warpN * 16 + nt * 8 + 2 * (lane & 3) + (p & 1);
                int b_ = row >> 8;
                int t_ = row & 255;
                int gate = col >> 10, within = col & 1023;
                int bnp = within >> 3, cwi = within & 7;
                g_G0p[(((size_t)t_ * NB + bnp) * 64 + b_) * 32 + gate * 8 + cwi] =
                    acc[mt][nt][p] + __ldg(&b0[col]);
            }
}

// ---------------- persistent merged recurrence ----------------
__device__ __forceinline__ void load_stage(uint32_t sb, int st, int i, int bn, int tid,
                                           const float* __restrict__ A0,
                                           const float* __restrict__ A1) {
    const int seg = i >> 3, ii = i & 7;
    const float* Asrc = seg ? A1 : A0;
#pragma unroll
    for (int j = 0; j < 4; j++) {
        int c = j * 512 + tid;
        int g = c >> 9, rem = c & 511, row = rem >> 3, kc = rem & 7;
        cp16(sb + ST_A(st, g) + row * 144 + kc * 16,
             Asrc + row * HH + ii * 128 + g * 32 + kc * 4);
    }
    const float* W0 = (seg ? g_Wh1p : g_Wh0p) + (size_t)bn * 32768;
#pragma unroll
    for (int j = 0; j < 2; j++) {
        int c = j * 512 + tid;
        int g = c >> 8, rem = c & 255, col = rem >> 3, kc = rem & 7;
        cp16(sb + ST_B(st, 0, g) + col * 144 + kc * 16,
             W0 + ((ii * 4 + g) * 32 + col) * 32 + kc * 4);
    }
    if (!seg) {
        const float* W1 = g_Wx1p + (size_t)bn * 32768;
#pragma unroll
        for (int j = 0; j < 2; j++) {
            int c = j * 512 + tid;
            int g = c >> 8, rem = c & 255, col = rem >> 3, kc = rem & 7;
            cp16(sb + ST_B(st, 1, g) + col * 144 + kc * 16,
                 W1 + ((ii * 4 + g) * 32 + col) * 32 + kc * 4);
        }
    }
}

__device__ __forceinline__ void mma_iter(const float* __restrict__ sm, int st, int seg,
                                         int wk, int wn, int wm, int lane,
                                         float acc0[2][2][4], float acc1[2][2][4]) {
    const float* A  = sm + (ST_A(st, wk) >> 2);
    const float* B0 = sm + (ST_B(st, 0, wk) >> 2);
    const float* B1 = sm + (ST_B(st, 1, wk) >> 2);
    const int l2 = lane >> 2, la3 = lane & 3;
    const int r0 = wm * 32 + l2;
#pragma unroll
    for (int ks = 0; ks < 4; ks++) {
        const int kb = ks * 8 + la3;
        uint32_t a[2][4];
#pragma unroll
        for (int mt = 0; mt < 2; mt++) {
            const int rb = (r0 + mt * 16) * 36;
            a[mt][0] = __float_as_uint(A[rb + kb]);
            a[mt][1] = __float_as_uint(A[rb + 8 * 36 + kb]);
            a[mt][2] = __float_as_uint(A[rb + kb + 4]);
            a[mt][3] = __float_as_uint(A[rb + 8 * 36 + kb + 4]);
        }
#pragma unroll
        for (int nt = 0; nt < 2; nt++) {
            const int cb = (wn * 16 + nt * 8 + l2) * 36;
            uint32_t b[2];
            b[0] = __float_as_uint(B0[cb + kb]);
            b[1] = __float_as_uint(B0[cb + kb + 4]);
            float (*accS)[4] = seg ? acc1[nt] : acc0[nt];
#pragma unroll
            for (int mt = 0; mt < 2; mt++) mma8(accS[mt], a[mt], b);
            if (!seg) {
                uint32_t b2[2];
                b2[0] = __float_as_uint(B1[cb + kb]);
                b2[1] = __float_as_uint(B1[cb + kb + 4]);
#pragma unroll
                for (int mt = 0; mt < 2; mt++) mma8(acc1[nt][mt], a[mt], b2);
            }
        }
    }
}

__global__ void __launch_bounds__(512, 1) lstm_persist() {
    extern __shared__ float sm[];
    uint32_t sb = (uint32_t)__cvta_generic_to_shared(sm);
    const int tid = threadIdx.x, lane = tid & 31, warp = tid >> 5;
    const int wk = warp & 3, wn = (warp >> 2) & 1, wm = warp >> 3;
    const int bn = blockIdx.x;
    const int erow = tid >> 3, ecw = tid & 7;   // epilogue ownership

    float c0r = 0.f, c1r = 0.f;
    unsigned tgt = 0;

    for (int s = 0; s <= 256; s++) {
        const float* A0 = g_h0r[s & 1];
        const float* A1 = g_h1r[(s + 1) & 1];

        load_stage(sb, 0, 0, bn, tid, A0, A1);
        {
            const float* g0src = g_G0p + ((size_t)min(s, 255) * NB + bn) * 2048;
            cp16(sb + G0_OFF + tid * 16, g0src + tid * 4);
        }
        CP_COMMIT();
        load_stage(sb, 1, 1, bn, tid, A0, A1);
        CP_COMMIT();

        float acc0[2][2][4], acc1[2][2][4];
#pragma unroll
        for (int n = 0; n < 2; n++)
#pragma unroll
            for (int m = 0; m < 2; m++)
#pragma unroll
                for (int p = 0; p < 4; p++) { acc0[n][m][p] = 0.f; acc1[n][m][p] = 0.f; }

        for (int i = 0; i < 16; i++) {
            CP_WAIT1();
            __syncthreads();
            if (i + 2 < 16) load_stage(sb, (i + 2) % 3, i + 2, bn, tid, A0, A1);
            CP_COMMIT();
            mma_iter(sm, i % 3, i >> 3, wk, wn, wm, lane, acc0, acc1);
        }
        CP_WAIT0();
        __syncthreads();

        // dump accumulators to red buffer (aliases stage region)
#pragma unroll
        for (int L = 0; L < 2; L++) {
            float (*acc)[2][4] = L ? acc1 : acc0;
#pragma unroll
            for (int nt = 0; nt < 2; nt++)
#pragma unroll
                for (int mt = 0; mt < 2; mt++)
#pragma unroll
                    for (int p = 0; p < 4; p++) {
                        int row = wm * 32 + mt * 16 + (lane >> 2) + ((p & 2) ? 8 : 0);
                        int col = wn * 16 + nt * 8 + 2 * (lane & 3) + (p & 1);
                        sm[((wk * 2 + L) * 64 + row) * 36 + col] = acc[nt][mt][p];
                    }
        }
        __syncthreads();

        // epilogue: one h element per thread per layer
        {
            float v0[4], v1[4];
#pragma unroll
            for (int g = 0; g < 4; g++) {
                float s0 = 0.f, s1 = 0.f;
#pragma unroll
                for (int k = 0; k < 4; k++) {
                    s0 += sm[((k * 2 + 0) * 64 + erow) * 36 + g * 8 + ecw];
                    s1 += sm[((k * 2 + 1) * 64 + erow) * 36 + g * 8 + ecw];
                }
                v0[g] = s0; v1[g] = s1;
            }
            const float* g0f = sm + (G0_OFF >> 2);
            const int hidx = erow * HH + bn * 8 + ecw;
            if (s < 256) {
                float iv = v0[0] + g0f[erow * 32 + ecw];
                float fv = v0[1] + g0f[erow * 32 + 8 + ecw];
                float gv = v0[2] + g0f[erow * 32 + 16 + ecw];
                float ov = v0[3] + g0f[erow * 32 + 24 + ecw];
                float cn = sigf(fv) * c0r + sigf(iv) * tanhf_(gv);
                c0r = cn;
                g_h0r[(s + 1) & 1][hidx] = __uint_as_float(f2tf(sigf(ov) * tanhf_(cn)));
            }
            if (s >= 1) {
                float iv = v1[0] + __ldg(&g_b1p[bn * 32 + ecw]);
                float fv = v1[1] + __ldg(&g_b1p[bn * 32 + 8 + ecw]);
                float gv = v1[2] + __ldg(&g_b1p[bn * 32 + 16 + ecw]);
                float ov = v1[3] + __ldg(&g_b1p[bn * 32 + 24 + ecw]);
                float cn = sigf(fv) * c1r + sigf(iv) * tanhf_(gv);
                c1r = cn;
                float h = sigf(ov) * tanhf_(cn);
                g_h1r[s & 1][hidx] = __uint_as_float(f2tf(h));
                g_h1e[hidx] = h;
            }
        }

        // grid barrier
        __syncthreads();
        tgt += NB;
        if (tid == 0) {
            __threadfence();
            atomicAdd(&g_bar, 1u);
            while (*(volatile unsigned*)&g_bar < tgt) {}
            __threadfence();
        }
        __syncthreads();
    }
}

__global__ void copy_out_kernel(float* __restrict__ out) {
    int i = blockIdx.x * blockDim.x + threadIdx.x;
    if (i < BB * HH) out[i] = g_h1e[i];
}

// ---------------- launch ----------------
extern "C" void kernel_launch(void* const* d_in, const int* in_sizes, int n_in,
                              void* d_out, int out_size) {
    const float* x   = (const float*)d_in[0];
    const float* Wx0 = (const float*)d_in[1];
    const float* Wh0 = (const float*)d_in[2];
    const float* b0  = (const float*)d_in[3];
    const float* Wx1 = (const float*)d_in[4];
    const float* Wh1 = (const float*)d_in[5];
    const float* b1  = (const float*)d_in[6];
    (void)in_sizes; (void)n_in; (void)out_size;

    cudaFuncSetAttribute(lstm_persist, cudaFuncAttributeMaxDynamicSharedMemorySize, SMEM_BYTES);

    convert_pack_kernel<<<4096, 256>>>(Wx0, Wh0, Wx1, Wh1, b1);
    init_kernel<<<256, 256>>>();

    dim3 grid_x(G4 / 64, (BB * TT) / 128);
    xgemm_kernel<<<grid_x, 256>>>(x, b0);

    lstm_persist<<<NB, 512, SMEM_BYTES>>>();

    copy_out_kernel<<<(BB * HH + 255) / 256, 256>>>((float*)d_out);
}

// round 5
// speedup vs baseline: 1.2996x; 1.2996x over previous
#include <cuda_runtime.h>
#include <cstdint>
#include <cstddef>

#define BB   64
#define TT   256
#define DD   1024
#define HH   1024
#define G4   4096
#define NB   128

// ---------------- device scratch ----------------
__device__ float g_G0p[(size_t)TT * NB * 64 * 32];  // [t][bn][row64][gate8*4]
__device__ float g_Wx0c[DD * G4];
__device__ float g_Wh0p[HH * G4];   // packed [bn][kseg32][col32][kin32]
__device__ float g_Wx1p[HH * G4];
__device__ float g_Wh1p[HH * G4];
__device__ float g_b1p[NB * 32];
__device__ float g_h0r[2][BB * HH];
__device__ float g_h1r[2][BB * HH];
__device__ float g_h1e[BB * HH];
__device__ unsigned g_bar;

// ---------------- smem layout (bytes) ----------------
// stage: A = 4 groups x 64 rows x 36 floats = 36864 B
//        B = 2 sets x 4 groups x 32 cols x 36 floats = 36864 B   -> 73728 B
#define STAGE_B   73728
#define B_REGION  36864
#define BSET_OFF  18432
#define G0_OFF    221184
#define SMEM_BYTES 229376

// ---------------- helpers ----------------
__device__ __forceinline__ uint32_t f2tf(float x) {
    uint32_t r; asm("cvt.rna.tf32.f32 %0, %1;" : "=r"(r) : "f"(x)); return r;
}
__device__ __forceinline__ void mma8(float* d, const uint32_t* a, const uint32_t* b) {
    asm volatile(
        "mma.sync.aligned.m16n8k8.row.col.f32.tf32.tf32.f32 "
        "{%0,%1,%2,%3}, {%4,%5,%6,%7}, {%8,%9}, {%0,%1,%2,%3};"
        : "+f"(d[0]), "+f"(d[1]), "+f"(d[2]), "+f"(d[3])
        : "r"(a[0]), "r"(a[1]), "r"(a[2]), "r"(a[3]), "r"(b[0]), "r"(b[1]));
}
__device__ __forceinline__ void ldsm4(uint32_t* r, uint32_t addr) {
    asm volatile("ldmatrix.sync.aligned.m8n8.x4.shared.b16 {%0,%1,%2,%3}, [%4];"
        : "=r"(r[0]), "=r"(r[1]), "=r"(r[2]), "=r"(r[3]) : "r"(addr));
}
__device__ __forceinline__ void cp16(uint32_t s, const void* g) {
    asm volatile("cp.async.cg.shared.global [%0], [%1], 16;" :: "r"(s), "l"(g));
}
#define CP_COMMIT() asm volatile("cp.async.commit_group;")
#define CP_WAIT1()  asm volatile("cp.async.wait_group 1;")
#define CP_WAIT0()  asm volatile("cp.async.wait_group 0;")

__device__ __forceinline__ float sigf(float x)   { return 1.f / (1.f + __expf(-x)); }
__device__ __forceinline__ float tanhf_(float x) { return 2.f / (1.f + __expf(-2.f * x)) - 1.f; }

// ---------------- convert + pack ----------------
__global__ void convert_pack_kernel(const float* __restrict__ Wx0, const float* __restrict__ Wh0,
                                    const float* __restrict__ Wx1, const float* __restrict__ Wh1,
                                    const float* __restrict__ b1) {
    const int n1 = 1 << 22;
    const int stride = gridDim.x * blockDim.x;
    for (int idx = blockIdx.x * blockDim.x + threadIdx.x; idx < 4 * n1; idx += stride) {
        int w = idx >> 22;
        int d = idx & (n1 - 1);
        if (w == 0) {
            g_Wx0c[d] = __uint_as_float(f2tf(Wx0[d]));
        } else {
            int kin = d & 31, col = (d >> 5) & 31, kseg = (d >> 10) & 31, bn = d >> 15;
            int gate = col >> 3, cw = col & 7;
            int src = (kseg * 32 + kin) * G4 + gate * HH + bn * 8 + cw;
            float v = (w == 1) ? Wh0[src] : (w == 2) ? Wx1[src] : Wh1[src];
            float* dst = (w == 1) ? g_Wh0p : (w == 2) ? g_Wx1p : g_Wh1p;
            dst[d] = __uint_as_float(f2tf(v));
        }
    }
    for (int i = blockIdx.x * blockDim.x + threadIdx.x; i < NB * 32; i += stride) {
        int bn = i >> 5, c = i & 31, gate = c >> 3, cw = c & 7;
        g_b1p[i] = b1[gate * HH + bn * 8 + cw];
    }
}

__global__ void init_kernel() {
    int i = blockIdx.x * blockDim.x + threadIdx.x;
    if (i < BB * HH) {
        g_h0r[0][i] = 0.f; g_h0r[1][i] = 0.f;
        g_h1r[0][i] = 0.f; g_h1r[1][i] = 0.f;
    }
    if (i == 0) g_bar = 0u;
}

// ---------------- precompute G0 = X @ Wx0 + b0 (packed) ----------------
__global__ void __launch_bounds__(256) xgemm_kernel(const float* __restrict__ x,
                                                    const float* __restrict__ b0) {
    __shared__ uint32_t sA[128][17];
    __shared__ float    sB[16][64];
    const int tid  = threadIdx.x;
    const int lane = tid & 31;
    const int warp = tid >> 5;
    const int warpM = warp & 1;
    const int warpN = warp >> 1;
    const int bm = blockIdx.y * 128;
    const int bn = blockIdx.x * 64;

    float acc[4][2][4];
#pragma unroll
    for (int i = 0; i < 4; i++)
#pragma unroll
        for (int j = 0; j < 2; j++)
#pragma unroll
            for (int p = 0; p < 4; p++) acc[i][j][p] = 0.f;

    const int arow = tid >> 1;
    const int acb  = (tid & 1) * 8;
    const int brow = tid >> 4;
    const int bcol = (tid & 15) * 4;

    for (int k0 = 0; k0 < DD; k0 += 16) {
        {
            const float* s = x + (size_t)(bm + arow) * DD + k0 + acb;
            float4 v0 = *(const float4*)s;
            float4 v1 = *(const float4*)(s + 4);
            sA[arow][acb + 0] = f2tf(v0.x); sA[arow][acb + 1] = f2tf(v0.y);
            sA[arow][acb + 2] = f2tf(v0.z); sA[arow][acb + 3] = f2tf(v0.w);
            sA[arow][acb + 4] = f2tf(v1.x); sA[arow][acb + 5] = f2tf(v1.y);
            sA[arow][acb + 6] = f2tf(v1.z); sA[arow][acb + 7] = f2tf(v1.w);
        }
        *(float4*)&sB[brow][bcol] =
            *(const float4*)(g_Wx0c + (size_t)(k0 + brow) * G4 + bn + bcol);
        __syncthreads();
#pragma unroll
        for (int ks = 0; ks < 2; ks++) {
            uint32_t a[4][4];
            const int kb = ks * 8 + (lane & 3);
#pragma unroll
            for (int mt = 0; mt < 4; mt++) {
                const int r = warpM * 64 + mt * 16 + (lane >> 2);
                a[mt][0] = sA[r][kb];     a[mt][1] = sA[r + 8][kb];
                a[mt][2] = sA[r][kb + 4]; a[mt][3] = sA[r + 8][kb + 4];
            }
#pragma unroll
            for (int nt = 0; nt < 2; nt++) {
                uint32_t b[2];
                const int c = warpN * 16 + nt * 8 + (lane >> 2);
                b[0] = __float_as_uint(sB[kb][c]);
                b[1] = __float_as_uint(sB[kb + 4][c]);
#pragma unroll
                for (int mt = 0; mt < 4; mt++) mma8(acc[mt][nt], a[mt], b);
            }
        }
        __syncthreads();
    }
#pragma unroll
    for (int mt = 0; mt < 4; mt++)
#pragma unroll
        for (int nt = 0; nt < 2; nt++)
#pragma unroll
            for (int p = 0; p < 4; p++) {
                int row = bm + warpM * 64 + mt * 16 + (lane >> 2) + ((p & 2) ? 8 : 0);
                int col = bn + warpN * 16 + nt * 8 + 2 * (lane & 3) + (p & 1);
                int b_ = row >> 8;
                int t_ = row & 255;
                int gate = col >> 10, within = col & 1023;
                int bnp = within >> 3, cwi = within & 7;
                g_G0p[(((size_t)t_ * NB + bnp) * 64 + b_) * 32 + gate * 8 + cwi] =
                    acc[mt][nt][p] + __ldg(&b0[col]);
            }
}

// ---------------- persistent merged recurrence ----------------
__global__ void __launch_bounds__(512, 1) lstm_persist() {
    extern __shared__ float sm[];
    uint32_t sb = (uint32_t)__cvta_generic_to_shared(sm);
    const int tid = threadIdx.x, lane = tid & 31, warp = tid >> 5;
    const int wk = warp & 3, wn = (warp >> 2) & 1, wm = warp >> 3;
    const int bn = blockIdx.x;
    const int erow = tid >> 3, ecw = tid & 7;

    // ---- precomputed cp.async offsets (per thread) ----
    uint32_t dstA[4], srcA[4];   // bytes
#pragma unroll
    for (int j = 0; j < 4; j++) {
        int c = j * 512 + tid;
        int g = c >> 9, rem = c & 511, row = rem >> 3, kc = rem & 7;
        dstA[j] = g * 9216u + row * 144u + kc * 16u;
        srcA[j] = (uint32_t)(row * HH + g * 32 + kc * 4) * 4u;
    }
    uint32_t dstB[2], srcB[2];
#pragma unroll
    for (int j = 0; j < 2; j++) {
        int c = j * 512 + tid;
        int g = c >> 8, rem = c & 255, col = rem >> 3, kc = rem & 7;
        dstB[j] = B_REGION + g * 4608u + col * 144u + kc * 16u;
        srcB[j] = (uint32_t)((g * 32 + col) * 32 + kc * 4) * 4u;
    }
    const size_t wbn = (size_t)bn * 131072u;   // bytes into packed W

    // ---- precomputed ldmatrix lane offsets ----
    const uint32_t laneoffA = ((wm * 32 + (lane & 15)) * 36u + (lane >> 4) * 4u) * 4u
                              + wk * 9216u;
    const uint32_t laneoffB = ((wn * 16 + ((lane >> 4) << 3) + (lane & 7)) * 36u
                               + ((lane >> 3) & 1) * 4u) * 4u
                              + B_REGION + wk * 4608u;

    float c0r = 0.f, c1r = 0.f;
    unsigned tgt = 0;

    for (int s = 0; s <= 256; s++) {
        const char* A0 = (const char*)g_h0r[s & 1];
        const char* A1 = (const char*)g_h1r[(s + 1) & 1];
        const char* W0base = (const char*)g_Wh0p + wbn;
        const char* W1base = (const char*)g_Wx1p + wbn;
        const char* W2base = (const char*)g_Wh1p + wbn;

        // issue a stage of loads for iteration i into stage st
        auto issue = [&](int st, int i) {
            const uint32_t stb = sb + st * STAGE_B;
            const int seg = i >> 3, ii = i & 7;
            const char* Ap = (seg ? A1 : A0) + ii * 512;
#pragma unroll
            for (int j = 0; j < 4; j++) cp16(stb + dstA[j], Ap + srcA[j]);
            const char* Wp = (seg ? W2base : W0base) + ii * 16384;
#pragma unroll
            for (int j = 0; j < 2; j++) cp16(stb + dstB[j], Wp + srcB[j]);
            if (!seg) {
                const char* Wq = W1base + ii * 16384;
#pragma unroll
                for (int j = 0; j < 2; j++) cp16(stb + dstB[j] + BSET_OFF, Wq + srcB[j]);
            }
        };

        issue(0, 0);
        {
            const float* g0src = g_G0p + ((size_t)min(s, 255) * NB + bn) * 2048;
            cp16(sb + G0_OFF + tid * 16, g0src + tid * 4);
        }
        CP_COMMIT();
        issue(1, 1);
        CP_COMMIT();

        float acc0[2][2][4], acc1[2][2][4];
#pragma unroll
        for (int n = 0; n < 2; n++)
#pragma unroll
            for (int m = 0; m < 2; m++)
#pragma unroll
                for (int p = 0; p < 4; p++) { acc0[n][m][p] = 0.f; acc1[n][m][p] = 0.f; }

        int st = 0, st2 = 2;
        for (int i = 0; i < 16; i++) {
            CP_WAIT1();
            __syncthreads();
            if (i + 2 < 16) issue(st2, i + 2);
            CP_COMMIT();

            const uint32_t sA  = sb + st * STAGE_B + laneoffA;
            const uint32_t sB0 = sb + st * STAGE_B + laneoffB;
            const int seg = i >> 3;
#pragma unroll
            for (int ks = 0; ks < 4; ks++) {
                uint32_t a0[4], a1[4], b0[4];
                ldsm4(a0, sA + ks * 32);
                ldsm4(a1, sA + 16 * 144 + ks * 32);
                ldsm4(b0, sB0 + ks * 32);
                if (seg) {
                    mma8(acc1[0][0], a0, b0);     mma8(acc1[0][1], a1, b0);
                    mma8(acc1[1][0], a0, b0 + 2); mma8(acc1[1][1], a1, b0 + 2);
                } else {
                    mma8(acc0[0][0], a0, b0);     mma8(acc0[0][1], a1, b0);
                    mma8(acc0[1][0], a0, b0 + 2); mma8(acc0[1][1], a1, b0 + 2);
                    uint32_t b1[4];
                    ldsm4(b1, sB0 + BSET_OFF + ks * 32);
                    mma8(acc1[0][0], a0, b1);     mma8(acc1[0][1], a1, b1);
                    mma8(acc1[1][0], a0, b1 + 2); mma8(acc1[1][1], a1, b1 + 2);
                }
            }
            st = (st == 2) ? 0 : st + 1;
            st2 = (st2 == 2) ? 0 : st2 + 1;
        }
        CP_WAIT0();
        __syncthreads();

        // dump accumulators (float2 stores; aliases stage region)
        {
            const int row0 = wm * 32 + (lane >> 2);
            const int colb = wn * 16 + 2 * (lane & 3);
#pragma unroll
            for (int L = 0; L < 2; L++) {
                float (*acc)[2][4] = L ? acc1 : acc0;
                const int base = (wk * 2 + L) * 64;
#pragma unroll
                for (int nt = 0; nt < 2; nt++)
#pragma unroll
                    for (int mt = 0; mt < 2; mt++) {
                        const int r = base + row0 + mt * 16;
                        const int c = colb + nt * 8;
                        *(float2*)&sm[r * 36 + c] =
                            make_float2(acc[nt][mt][0], acc[nt][mt][1]);
                        *(float2*)&sm[(r + 8) * 36 + c] =
                            make_float2(acc[nt][mt][2], acc[nt][mt][3]);
                    }
            }
        }
        __syncthreads();

        // epilogue: one h element per thread per layer
        {
            float v0[4], v1[4];
#pragma unroll
            for (int g = 0; g < 4; g++) {
                float s0 = 0.f, s1 = 0.f;
#pragma unroll
                for (int k = 0; k < 4; k++) {
                    s0 += sm[((k * 2 + 0) * 64 + erow) * 36 + g * 8 + ecw];
                    s1 += sm[((k * 2 + 1) * 64 + erow) * 36 + g * 8 + ecw];
                }
                v0[g] = s0; v1[g] = s1;
            }
            const float* g0f = sm + (G0_OFF >> 2);
            const int hidx = erow * HH + bn * 8 + ecw;
            if (s < 256) {
                float iv = v0[0] + g0f[erow * 32 + ecw];
                float fv = v0[1] + g0f[erow * 32 + 8 + ecw];
                float gv = v0[2] + g0f[erow * 32 + 16 + ecw];
                float ov = v0[3] + g0f[erow * 32 + 24 + ecw];
                float cn = sigf(fv) * c0r + sigf(iv) * tanhf_(gv);
                c0r = cn;
                g_h0r[(s + 1) & 1][hidx] = __uint_as_float(f2tf(sigf(ov) * tanhf_(cn)));
            }
            if (s >= 1) {
                float iv = v1[0] + __ldg(&g_b1p[bn * 32 + ecw]);
                float fv = v1[1] + __ldg(&g_b1p[bn * 32 + 8 + ecw]);
                float gv = v1[2] + __ldg(&g_b1p[bn * 32 + 16 + ecw]);
                float ov = v1[3] + __ldg(&g_b1p[bn * 32 + 24 + ecw]);
                float cn = sigf(fv) * c1r + sigf(iv) * tanhf_(gv);
                c1r = cn;
                float h = sigf(ov) * tanhf_(cn);
                g_h1r[s & 1][hidx] = __uint_as_float(f2tf(h));
                g_h1e[hidx] = h;
            }
        }

        // grid barrier
        __syncthreads();
        tgt += NB;
        if (tid == 0) {
            __threadfence();
            atomicAdd(&g_bar, 1u);
            while (*(volatile unsigned*)&g_bar < tgt) {}
            __threadfence();
        }
        __syncthreads();
    }
}

__global__ void copy_out_kernel(float* __restrict__ out) {
    int i = blockIdx.x * blockDim.x + threadIdx.x;
    if (i < BB * HH) out[i] = g_h1e[i];
}

// ---------------- launch ----------------
extern "C" void kernel_launch(void* const* d_in, const int* in_sizes, int n_in,
                              void* d_out, int out_size) {
    const float* x   = (const float*)d_in[0];
    const float* Wx0 = (const float*)d_in[1];
    const float* Wh0 = (const float*)d_in[2];
    const float* b0  = (const float*)d_in[3];
    const float* Wx1 = (const float*)d_in[4];
    const float* Wh1 = (const float*)d_in[5];
    const float* b1  = (const float*)d_in[6];
    (void)in_sizes; (void)n_in; (void)out_size;

    cudaFuncSetAttribute(lstm_persist, cudaFuncAttributeMaxDynamicSharedMemorySize, SMEM_BYTES);

    convert_pack_kernel<<<4096, 256>>>(Wx0, Wh0, Wx1, Wh1, b1);
    init_kernel<<<256, 256>>>();

    dim3 grid_x(G4 / 64, (BB * TT) / 128);
    xgemm_kernel<<<grid_x, 256>>>(x, b0);

    lstm_persist<<<NB, 512, SMEM_BYTES>>>();

    copy_out_kernel<<<(BB * HH + 255) / 256, 256>>>((float*)d_out);
}

// round 7
// speedup vs baseline: 1.5894x; 1.2230x over previous
#include <cuda_runtime.h>
#include <cstdint>
#include <cstddef>

#define BB   64
#define TT   256
#define DD   1024
#define HH   1024
#define G4   4096
#define NB   128

// ---------------- device scratch ----------------
__device__ float g_G0p[(size_t)TT * NB * 64 * 32];  // [t][bn][row64][gate8*4]
__device__ float g_Wx0p[DD * G4];   // tf32-rounded, packed col-major [col4096][k1024]
__device__ float g_Wh0p[HH * G4];   // packed [bn][kseg32][col32][kin32]
__device__ float g_Wx1p[HH * G4];
__device__ float g_Wh1p[HH * G4];
__device__ float g_b1p[NB * 32];
__device__ float g_h0r[2][BB * HH];
__device__ float g_h1r[2][BB * HH];
__device__ float g_h1e[BB * HH];
__device__ unsigned g_bar;

// ---------------- smem layout: recurrence (bytes) ----------------
#define STAGE_B   73728
#define B_REGION  36864
#define BSET_OFF  18432
#define G0_OFF    221184
#define SMEM_BYTES 229376

// ---------------- helpers ----------------
__device__ __forceinline__ uint32_t f2tf(float x) {
    uint32_t r; asm("cvt.rna.tf32.f32 %0, %1;" : "=r"(r) : "f"(x)); return r;
}
__device__ __forceinline__ void mma8(float* d, const uint32_t* a, const uint32_t* b) {
    asm volatile(
        "mma.sync.aligned.m16n8k8.row.col.f32.tf32.tf32.f32 "
        "{%0,%1,%2,%3}, {%4,%5,%6,%7}, {%8,%9}, {%0,%1,%2,%3};"
        : "+f"(d[0]), "+f"(d[1]), "+f"(d[2]), "+f"(d[3])
        : "r"(a[0]), "r"(a[1]), "r"(a[2]), "r"(a[3]), "r"(b[0]), "r"(b[1]));
}
__device__ __forceinline__ void ldsm4(uint32_t* r, uint32_t addr) {
    asm volatile("ldmatrix.sync.aligned.m8n8.x4.shared.b16 {%0,%1,%2,%3}, [%4];"
        : "=r"(r[0]), "=r"(r[1]), "=r"(r[2]), "=r"(r[3]) : "r"(addr));
}
__device__ __forceinline__ void cp16(uint32_t s, const void* g) {
    asm volatile("cp.async.cg.shared.global [%0], [%1], 16;" :: "r"(s), "l"(g));
}
#define CP_COMMIT() asm volatile("cp.async.commit_group;")
#define CP_WAIT1()  asm volatile("cp.async.wait_group 1;")
#define CP_WAIT0()  asm volatile("cp.async.wait_group 0;")

__device__ __forceinline__ float sigf(float x)   { return 1.f / (1.f + __expf(-x)); }
__device__ __forceinline__ float tanhf_(float x) { return 2.f / (1.f + __expf(-2.f * x)) - 1.f; }

// ---------------- convert + pack ----------------
__global__ void convert_pack_kernel(const float* __restrict__ Wx0, const float* __restrict__ Wh0,
                                    const float* __restrict__ Wx1, const float* __restrict__ Wh1,
                                    const float* __restrict__ b1) {
    const int n1 = 1 << 22;
    const int stride = gridDim.x * blockDim.x;
    for (int idx = blockIdx.x * blockDim.x + threadIdx.x; idx < 4 * n1; idx += stride) {
        int w = idx >> 22;
        int d = idx & (n1 - 1);
        if (w == 0) {
            // packed col-major: d = col*1024 + k
            int k = d & 1023, col = d >> 10;
            g_Wx0p[d] = __uint_as_float(f2tf(Wx0[(size_t)k * G4 + col]));
        } else {
            int kin = d & 31, col = (d >> 5) & 31, kseg = (d >> 10) & 31, bn = d >> 15;
            int gate = col >> 3, cw = col & 7;
            int src = (kseg * 32 + kin) * G4 + gate * HH + bn * 8 + cw;
            float v = (w == 1) ? Wh0[src] : (w == 2) ? Wx1[src] : Wh1[src];
            float* dst = (w == 1) ? g_Wh0p : (w == 2) ? g_Wx1p : g_Wh1p;
            dst[d] = __uint_as_float(f2tf(v));
        }
    }
    for (int i = blockIdx.x * blockDim.x + threadIdx.x; i < NB * 32; i += stride) {
        int bn = i >> 5, c = i & 31, gate = c >> 3, cw = c & 7;
        g_b1p[i] = b1[gate * HH + bn * 8 + cw];
    }
}

__global__ void init_kernel() {
    int i = blockIdx.x * blockDim.x + threadIdx.x;
    if (i < BB * HH) {
        g_h0r[0][i] = 0.f; g_h0r[1][i] = 0.f;
        g_h1r[0][i] = 0.f; g_h1r[1][i] = 0.f;
    }
    if (i == 0) g_bar = 0u;
}

// ---------------- precompute G0 = X @ Wx0 + b0 (pipelined, ldmatrix) ----------------
// BM=128, BN=64, BK=32, 256 thr (8 warps: wm 0-3 x 32 rows, wn 0-1 x 32 cols), 3-stage cp.async
#define XSTAGE 27648   // A: 128x36 floats (18432B) + B: 64x36 floats (9216B)
#define XSMEM  (3 * XSTAGE)

__global__ void __launch_bounds__(256, 2) xgemm_kernel(const float* __restrict__ x,
                                                       const float* __restrict__ b0) {
    extern __shared__ float xsm[];
    uint32_t sb = (uint32_t)__cvta_generic_to_shared(xsm);
    const int tid = threadIdx.x, lane = tid & 31, warp = tid >> 5;
    const int wm = warp & 3, wn = warp >> 2;
    const int bm = blockIdx.y * 128;
    const int bn = blockIdx.x * 64;

    uint32_t dstA[4], srcA[4];
#pragma unroll
    for (int j = 0; j < 4; j++) {
        int c = j * 256 + tid, row = c >> 3, kc = c & 7;
        dstA[j] = row * 144u + kc * 16u;
        srcA[j] = (uint32_t)((bm + row) * DD + kc * 4) * 4u;
    }
    uint32_t dstB[2], srcB[2];
#pragma unroll
    for (int j = 0; j < 2; j++) {
        int c = j * 256 + tid, col = c >> 3, kc = c & 7;
        dstB[j] = 18432u + col * 144u + kc * 16u;
        srcB[j] = (uint32_t)((bn + col) * DD + kc * 4) * 4u;
    }
    const uint32_t laneoffA = ((wm * 32 + (lane & 15)) * 36u + (lane >> 4) * 4u) * 4u;
    const uint32_t laneoffB = 18432u + ((wn * 32 + ((lane >> 4) << 3) + (lane & 7)) * 36u
                                        + ((lane >> 3) & 1) * 4u) * 4u;

    auto issue = [&](int st, int k0) {
        const uint32_t stb = sb + st * XSTAGE;
        const char* xb = (const char*)x + (size_t)k0 * 4;
        const char* wb = (const char*)g_Wx0p + (size_t)k0 * 4;
#pragma unroll
        for (int j = 0; j < 4; j++) cp16(stb + dstA[j], xb + srcA[j]);
#pragma unroll
        for (int j = 0; j < 2; j++) cp16(stb + dstB[j], wb + srcB[j]);
    };

    float acc[2][4][4];
#pragma unroll
    for (int m = 0; m < 2; m++)
#pragma unroll
        for (int n = 0; n < 4; n++)
#pragma unroll
            for (int p = 0; p < 4; p++) acc[m][n][p] = 0.f;

    issue(0, 0); CP_COMMIT();
    issue(1, 32); CP_COMMIT();

    int st = 0, st2 = 2;
    for (int it = 0; it < 32; it++) {
        CP_WAIT1();
        __syncthreads();
        if (it + 2 < 32) issue(st2, (it + 2) * 32);
        CP_COMMIT();

        const uint32_t base = sb + st * XSTAGE;
#pragma unroll
        for (int ks = 0; ks < 4; ks++) {
            uint32_t a0[4], a1[4], b01[4], b23[4];
            ldsm4(a0, base + laneoffA + ks * 32);
            ldsm4(a1, base + laneoffA + 2304 + ks * 32);
            ldsm4(b01, base + laneoffB + ks * 32);
            ldsm4(b23, base + laneoffB + 2304 + ks * 32);
            mma8(acc[0][0], a0, b01);     mma8(acc[1][0], a1, b01);
            mma8(acc[0][1], a0, b01 + 2); mma8(acc[1][1], a1, b01 + 2);
            mma8(acc[0][2], a0, b23);     mma8(acc[1][2], a1, b23);
            mma8(acc[0][3], a0, b23 + 2); mma8(acc[1][3], a1, b23 + 2);
        }
        st = (st == 2) ? 0 : st + 1;
        st2 = (st2 == 2) ? 0 : st2 + 1;
    }

#pragma unroll
    for (int mt = 0; mt < 2; mt++)
#pragma unroll
        for (int nt = 0; nt < 4; nt++)
#pragma unroll
            for (int p = 0; p < 4; p++) {
                int row = bm + wm * 32 + mt * 16 + (lane >> 2) + ((p & 2) ? 8 : 0);
                int col = bn + wn * 32 + nt * 8 + 2 * (lane & 3) + (p & 1);
                int b_ = row >> 8;
                int t_ = row & 255;
                int gate = col >> 10, within = col & 1023;
                int bnp = within >> 3, cwi = within & 7;
                g_G0p[(((size_t)t_ * NB + bnp) * 64 + b_) * 32 + gate * 8 + cwi] =
                    acc[mt][nt][p] + __ldg(&b0[col]);
            }
}

// ---------------- persistent merged recurrence ----------------
__global__ void __launch_bounds__(512, 1) lstm_persist() {
    extern __shared__ float sm[];
    uint32_t sb = (uint32_t)__cvta_generic_to_shared(sm);
    const int tid = threadIdx.x, lane = tid & 31, warp = tid >> 5;
    const int wk = warp & 3, wn = (warp >> 2) & 1, wm = warp >> 3;
    const int bn = blockIdx.x;
    const int erow = tid >> 3, ecw = tid & 7;

    uint32_t dstA[4], srcA[4];
#pragma unroll
    for (int j = 0; j < 4; j++) {
        int c = j * 512 + tid;
        int g = c >> 9, rem = c & 511, row = rem >> 3, kc = rem & 7;
        dstA[j] = g * 9216u + row * 144u + kc * 16u;
        srcA[j] = (uint32_t)(row * HH + g * 32 + kc * 4) * 4u;
    }
    uint32_t dstB[2], srcB[2];
#pragma unroll
    for (int j = 0; j < 2; j++) {
        int c = j * 512 + tid;
        int g = c >> 8, rem = c & 255, col = rem >> 3, kc = rem & 7;
        dstB[j] = B_REGION + g * 4608u + col * 144u + kc * 16u;
        srcB[j] = (uint32_t)((g * 32 + col) * 32 + kc * 4) * 4u;
    }
    const size_t wbn = (size_t)bn * 131072u;
    const char* W0base = (const char*)g_Wh0p + wbn;
    const char* W1base = (const char*)g_Wx1p + wbn;
    const char* W2base = (const char*)g_Wh1p + wbn;

    const uint32_t laneoffA = ((wm * 32 + (lane & 15)) * 36u + (lane >> 4) * 4u) * 4u
                              + wk * 9216u;
    const uint32_t laneoffB = ((wn * 16 + ((lane >> 4) << 3) + (lane & 7)) * 36u
                               + ((lane >> 3) & 1) * 4u) * 4u
                              + B_REGION + wk * 4608u;

    auto issueB = [&](int st, int i) {
        const uint32_t stb = sb + st * STAGE_B;
        const int seg = i >> 3, ii = i & 7;
        const char* Wp = (seg ? W2base : W0base) + ii * 16384;
#pragma unroll
        for (int j = 0; j < 2; j++) cp16(stb + dstB[j], Wp + srcB[j]);
        if (!seg) {
            const char* Wq = W1base + ii * 16384;
#pragma unroll
            for (int j = 0; j < 2; j++) cp16(stb + dstB[j] + BSET_OFF, Wq + srcB[j]);
        }
    };
    auto issueA = [&](int st, int i, const char* A0, const char* A1) {
        const uint32_t stb = sb + st * STAGE_B;
        const int seg = i >> 3, ii = i & 7;
        const char* Ap = (seg ? A1 : A0) + ii * 512;
#pragma unroll
        for (int j = 0; j < 4; j++) cp16(stb + dstA[j], Ap + srcA[j]);
    };
    auto g0pref = [&](int t) {
        const float* g0src = g_G0p + ((size_t)t * NB + bn) * 2048;
        cp16(sb + G0_OFF + tid * 16, g0src + tid * 4);
    };

    float c0r = 0.f, c1r = 0.f;
    unsigned tgt = 0;

    // initial fill for superstep 0 (B for stages 0,1 + G0, then A)
    issueB(0, 0); issueB(1, 1); g0pref(0); CP_COMMIT();
    {
        const char* A0 = (const char*)g_h0r[0];
        const char* A1 = (const char*)g_h1r[1];
        issueA(0, 0, A0, A1); CP_COMMIT();
        issueA(1, 1, A0, A1); CP_COMMIT();
    }

    for (int s = 0; s <= 256; s++) {
        const char* A0 = (const char*)g_h0r[s & 1];
        const char* A1 = (const char*)g_h1r[(s + 1) & 1];

        float acc0[2][2][4], acc1[2][2][4];
#pragma unroll
        for (int n = 0; n < 2; n++)
#pragma unroll
            for (int m = 0; m < 2; m++)
#pragma unroll
                for (int p = 0; p < 4; p++) { acc0[n][m][p] = 0.f; acc1[n][m][p] = 0.f; }

        int st = 0, st2 = 2;
        for (int i = 0; i < 16; i++) {
            CP_WAIT1();
            __syncthreads();
            if (i + 2 < 16) { issueA(st2, i + 2, A0, A1); issueB(st2, i + 2); }
            CP_COMMIT();

            const uint32_t sA  = sb + st * STAGE_B + laneoffA;
            const uint32_t sB0 = sb + st * STAGE_B + laneoffB;
            const int seg = i >> 3;
#pragma unroll
            for (int ks = 0; ks < 4; ks++) {
                uint32_t a0[4], a1[4], b0[4];
                ldsm4(a0, sA + ks * 32);
                ldsm4(a1, sA + 16 * 144 + ks * 32);
                ldsm4(b0, sB0 + ks * 32);
                if (seg) {
                    mma8(acc1[0][0], a0, b0);     mma8(acc1[0][1], a1, b0);
                    mma8(acc1[1][0], a0, b0 + 2); mma8(acc1[1][1], a1, b0 + 2);
                } else {
                    uint32_t b1[4];
                    ldsm4(b1, sB0 + BSET_OFF + ks * 32);
                    mma8(acc0[0][0], a0, b0);     mma8(acc0[0][1], a1, b0);
                    mma8(acc0[1][0], a0, b0 + 2); mma8(acc0[1][1], a1, b0 + 2);
                    mma8(acc1[0][0], a0, b1);     mma8(acc1[0][1], a1, b1);
                    mma8(acc1[1][0], a0, b1 + 2); mma8(acc1[1][1], a1, b1 + 2);
                }
            }
            st = (st == 2) ? 0 : st + 1;
            st2 = (st2 == 2) ? 0 : st2 + 1;
        }
        CP_WAIT0();
        __syncthreads();

        // dump accumulators (aliases stage region)
        {
            const int row0 = wm * 32 + (lane >> 2);
            const int colb = wn * 16 + 2 * (lane & 3);
#pragma unroll
            for (int L = 0; L < 2; L++) {
                float (*acc)[2][4] = L ? acc1 : acc0;
                const int base = (wk * 2 + L) * 64;
#pragma unroll
                for (int nt = 0; nt < 2; nt++)
#pragma unroll
                    for (int mt = 0; mt < 2; mt++) {
                        const int r = base + row0 + mt * 16;
                        const int c = colb + nt * 8;
                        *(float2*)&sm[r * 36 + c] =
                            make_float2(acc[nt][mt][0], acc[nt][mt][1]);
                        *(float2*)&sm[(r + 8) * 36 + c] =
                            make_float2(acc[nt][mt][2], acc[nt][mt][3]);
                    }
            }
        }
        __syncthreads();

        // epilogue
        {
            float v0[4], v1[4];
#pragma unroll
            for (int g = 0; g < 4; g++) {
                float s0 = 0.f, s1 = 0.f;
#pragma unroll
                for (int k = 0; k < 4; k++) {
                    s0 += sm[((k * 2 + 0) * 64 + erow) * 36 + g * 8 + ecw];
                    s1 += sm[((k * 2 + 1) * 64 + erow) * 36 + g * 8 + ecw];
                }
                v0[g] = s0; v1[g] = s1;
            }
            const float* g0f = sm + (G0_OFF >> 2);
            const int hidx = erow * HH + bn * 8 + ecw;
            if (s < 256) {
                float iv = v0[0] + g0f[erow * 32 + ecw];
                float fv = v0[1] + g0f[erow * 32 + 8 + ecw];
                float gv = v0[2] + g0f[erow * 32 + 16 + ecw];
                float ov = v0[3] + g0f[erow * 32 + 24 + ecw];
                float cn = sigf(fv) * c0r + sigf(iv) * tanhf_(gv);
                c0r = cn;
                g_h0r[(s + 1) & 1][hidx] = __uint_as_float(f2tf(sigf(ov) * tanhf_(cn)));
            }
            if (s >= 1) {
                float iv = v1[0] + __ldg(&g_b1p[bn * 32 + ecw]);
                float fv = v1[1] + __ldg(&g_b1p[bn * 32 + 8 + ecw]);
                float gv = v1[2] + __ldg(&g_b1p[bn * 32 + 16 + ecw]);
                float ov = v1[3] + __ldg(&g_b1p[bn * 32 + 24 + ecw]);
                float cn = sigf(fv) * c1r + sigf(iv) * tanhf_(gv);
                c1r = cn;
                float h = sigf(ov) * tanhf_(cn);
                g_h1r[s & 1][hidx] = __uint_as_float(f2tf(h));
                g_h1e[hidx] = h;
            }
        }
        __syncthreads();   // red-buffer reads done before B prefetch overwrites stages 0/1

        // prefetch next superstep's weights + G0 (barrier-independent), overlap with spin
        if (s < 256) {
            issueB(0, 0); issueB(1, 1); g0pref(min(s + 1, 255));
        }
        CP_COMMIT();

        // grid barrier
        tgt += NB;
        if (tid == 0) {
            __threadfence();
            atomicAdd(&g_bar, 1u);
            while (*(volatile unsigned*)&g_bar < tgt) {}
            __threadfence();
        }
        __syncthreads();

        // A loads depend on the barrier (h produced by other blocks)
        if (s < 256) {
            const char* A0n = (const char*)g_h0r[(s + 1) & 1];
            const char* A1n = (const char*)g_h1r[s & 1];
            issueA(0, 0, A0n, A1n); CP_COMMIT();
            issueA(1, 1, A0n, A1n); CP_COMMIT();
        }
    }
}

__global__ void copy_out_kernel(float* __restrict__ out) {
    int i = blockIdx.x * blockDim.x + threadIdx.x;
    if (i < BB * HH) out[i] = g_h1e[i];
}

// ---------------- launch ----------------
extern "C" void kernel_launch(void* const* d_in, const int* in_sizes, int n_in,
                              void* d_out, int out_size) {
    const float* x   = (const float*)d_in[0];
    const float* Wx0 = (const float*)d_in[1];
    const float* Wh0 = (const float*)d_in[2];
    const float* b0  = (const float*)d_in[3];
    const float* Wx1 = (const float*)d_in[4];
    const float* Wh1 = (const float*)d_in[5];
    const float* b1  = (const float*)d_in[6];
    (void)in_sizes; (void)n_in; (void)out_size;

    cudaFuncSetAttribute(lstm_persist, cudaFuncAttributeMaxDynamicSharedMemorySize, SMEM_BYTES);
    cudaFuncSetAttribute(xgemm_kernel, cudaFuncAttributeMaxDynamicSharedMemorySize, XSMEM);

    convert_pack_kernel<<<4096, 256>>>(Wx0, Wh0, Wx1, Wh1, b1);
    init_kernel<<<256, 256>>>();

    dim3 grid_x(G4 / 64, (BB * TT) / 128);   // (64, 128)
    xgemm_kernel<<<grid_x, 256, XSMEM>>>(x, b0);

    lstm_persist<<<NB, 512, SMEM_BYTES>>>();

    copy_out_kernel<<<(BB * HH + 255) / 256, 256>>>((float*)d_out);
}

// round 8
// speedup vs baseline: 2.3782x; 1.4963x over previous
#include <cuda_runtime.h>
#include <cuda_fp16.h>
#include <cstdint>
#include <cstddef>

#define BB   64
#define TT   256
#define DD   1024
#define HH   1024
#define G4   4096
#define NB   128

// ---------------- device scratch ----------------
__device__ float  g_G0p[(size_t)TT * NB * 64 * 32];  // [t][bn][row64][gate8*4]
__device__ float  g_Wx0p[DD * G4];     // tf32-rounded, col-major [col4096][k1024] (xgemm)
__device__ __half g_Wh0h[HH * G4];     // fp16 packed [bn][ii8][col32][kin128]
__device__ __half g_Wx1h[HH * G4];
__device__ __half g_Wh1h[HH * G4];
__device__ float  g_b1p[NB * 32];
__device__ __half g_h0h[2][BB * HH];   // fp16 hidden (ping-pong)
__device__ __half g_h1h[2][BB * HH];
__device__ float  g_h1e[BB * HH];      // exact h1 for output
__device__ unsigned g_bar;

// ---------------- smem layout: recurrence (bytes) ----------------
// stage: A = 64 rows x 272B = 17408 ; B = 2 sets x 32 cols x 272B = 17408
#define STAGE_B   34816
#define B_REGION  17408
#define BSET_OFF  8704
#define G0_OFF    104448          // 3*STAGE_B
#define SMEM_BYTES 112640         // + 8KB G0

// ---------------- helpers ----------------
__device__ __forceinline__ uint32_t f2tf(float x) {
    uint32_t r; asm("cvt.rna.tf32.f32 %0, %1;" : "=r"(r) : "f"(x)); return r;
}
__device__ __forceinline__ void mma_tf32(float* d, const uint32_t* a, const uint32_t* b) {
    asm volatile(
        "mma.sync.aligned.m16n8k8.row.col.f32.tf32.tf32.f32 "
        "{%0,%1,%2,%3}, {%4,%5,%6,%7}, {%8,%9}, {%0,%1,%2,%3};"
        : "+f"(d[0]), "+f"(d[1]), "+f"(d[2]), "+f"(d[3])
        : "r"(a[0]), "r"(a[1]), "r"(a[2]), "r"(a[3]), "r"(b[0]), "r"(b[1]));
}
__device__ __forceinline__ void mma_f16(float* d, const uint32_t* a, const uint32_t* b) {
    asm volatile(
        "mma.sync.aligned.m16n8k16.row.col.f32.f16.f16.f32 "
        "{%0,%1,%2,%3}, {%4,%5,%6,%7}, {%8,%9}, {%0,%1,%2,%3};"
        : "+f"(d[0]), "+f"(d[1]), "+f"(d[2]), "+f"(d[3])
        : "r"(a[0]), "r"(a[1]), "r"(a[2]), "r"(a[3]), "r"(b[0]), "r"(b[1]));
}
__device__ __forceinline__ void ldsm4(uint32_t* r, uint32_t addr) {
    asm volatile("ldmatrix.sync.aligned.m8n8.x4.shared.b16 {%0,%1,%2,%3}, [%4];"
        : "=r"(r[0]), "=r"(r[1]), "=r"(r[2]), "=r"(r[3]) : "r"(addr));
}
__device__ __forceinline__ void cp16(uint32_t s, const void* g) {
    asm volatile("cp.async.cg.shared.global [%0], [%1], 16;" :: "r"(s), "l"(g));
}
#define CP_COMMIT() asm volatile("cp.async.commit_group;")
#define CP_WAIT1()  asm volatile("cp.async.wait_group 1;")
#define CP_WAIT0()  asm volatile("cp.async.wait_group 0;")

__device__ __forceinline__ float sigf(float x)   { return 1.f / (1.f + __expf(-x)); }
__device__ __forceinline__ float tanhf_(float x) { return 2.f / (1.f + __expf(-2.f * x)) - 1.f; }

// ---------------- convert + pack ----------------
__global__ void convert_pack_kernel(const float* __restrict__ Wx0, const float* __restrict__ Wh0,
                                    const float* __restrict__ Wx1, const float* __restrict__ Wh1,
                                    const float* __restrict__ b1) {
    const int n1 = 1 << 22;
    const int stride = gridDim.x * blockDim.x;
    for (int idx = blockIdx.x * blockDim.x + threadIdx.x; idx < 4 * n1; idx += stride) {
        int w = idx >> 22;
        int d = idx & (n1 - 1);
        if (w == 0) {
            int k = d & 1023, col = d >> 10;
            g_Wx0p[d] = __uint_as_float(f2tf(Wx0[(size_t)k * G4 + col]));
        } else {
            // packed fp16: d = ((bn*8 + ii)*32 + col)*128 + kin
            int kin = d & 127, col = (d >> 7) & 31, ii = (d >> 12) & 7, bn = d >> 15;
            int gate = col >> 3, cw = col & 7;
            int k = ii * 128 + kin;
            int src = k * G4 + gate * HH + bn * 8 + cw;
            float v = (w == 1) ? Wh0[src] : (w == 2) ? Wx1[src] : Wh1[src];
            __half* dst = (w == 1) ? g_Wh0h : (w == 2) ? g_Wx1h : g_Wh1h;
            dst[d] = __float2half_rn(v);
        }
    }
    for (int i = blockIdx.x * blockDim.x + threadIdx.x; i < NB * 32; i += stride) {
        int bn = i >> 5, c = i & 31, gate = c >> 3, cw = c & 7;
        g_b1p[i] = b1[gate * HH + bn * 8 + cw];
    }
}

__global__ void init_kernel() {
    int i = blockIdx.x * blockDim.x + threadIdx.x;
    if (i < BB * HH) {
        g_h0h[0][i] = __float2half(0.f); g_h0h[1][i] = __float2half(0.f);
        g_h1h[0][i] = __float2half(0.f); g_h1h[1][i] = __float2half(0.f);
    }
    if (i == 0) g_bar = 0u;
}

// ---------------- precompute G0 = X @ Wx0 + b0 (pipelined, ldmatrix, tf32) ----------------
#define XSTAGE 27648
#define XSMEM  (3 * XSTAGE)

__global__ void __launch_bounds__(256, 2) xgemm_kernel(const float* __restrict__ x,
                                                       const float* __restrict__ b0) {
    extern __shared__ float xsm[];
    uint32_t sb = (uint32_t)__cvta_generic_to_shared(xsm);
    const int tid = threadIdx.x, lane = tid & 31, warp = tid >> 5;
    const int wm = warp & 3, wn = warp >> 2;
    const int bm = blockIdx.y * 128;
    const int bn = blockIdx.x * 64;

    uint32_t dstA[4], srcA[4];
#pragma unroll
    for (int j = 0; j < 4; j++) {
        int c = j * 256 + tid, row = c >> 3, kc = c & 7;
        dstA[j] = row * 144u + kc * 16u;
        srcA[j] = (uint32_t)((bm + row) * DD + kc * 4) * 4u;
    }
    uint32_t dstB[2], srcB[2];
#pragma unroll
    for (int j = 0; j < 2; j++) {
        int c = j * 256 + tid, col = c >> 3, kc = c & 7;
        dstB[j] = 18432u + col * 144u + kc * 16u;
        srcB[j] = (uint32_t)((bn + col) * DD + kc * 4) * 4u;
    }
    const uint32_t laneoffA = ((wm * 32 + (lane & 15)) * 36u + (lane >> 4) * 4u) * 4u;
    const uint32_t laneoffB = 18432u + ((wn * 32 + ((lane >> 4) << 3) + (lane & 7)) * 36u
                                        + ((lane >> 3) & 1) * 4u) * 4u;

    auto issue = [&](int st, int k0) {
        const uint32_t stb = sb + st * XSTAGE;
        const char* xb = (const char*)x + (size_t)k0 * 4;
        const char* wb = (const char*)g_Wx0p + (size_t)k0 * 4;
#pragma unroll
        for (int j = 0; j < 4; j++) cp16(stb + dstA[j], xb + srcA[j]);
#pragma unroll
        for (int j = 0; j < 2; j++) cp16(stb + dstB[j], wb + srcB[j]);
    };

    float acc[2][4][4];
#pragma unroll
    for (int m = 0; m < 2; m++)
#pragma unroll
        for (int n = 0; n < 4; n++)
#pragma unroll
            for (int p = 0; p < 4; p++) acc[m][n][p] = 0.f;

    issue(0, 0); CP_COMMIT();
    issue(1, 32); CP_COMMIT();

    int st = 0, st2 = 2;
    for (int it = 0; it < 32; it++) {
        CP_WAIT1();
        __syncthreads();
        if (it + 2 < 32) issue(st2, (it + 2) * 32);
        CP_COMMIT();

        const uint32_t base = sb + st * XSTAGE;
#pragma unroll
        for (int ks = 0; ks < 4; ks++) {
            uint32_t a0[4], a1[4], b01[4], b23[4];
            ldsm4(a0, base + laneoffA + ks * 32);
            ldsm4(a1, base + laneoffA + 2304 + ks * 32);
            ldsm4(b01, base + laneoffB + ks * 32);
            ldsm4(b23, base + laneoffB + 2304 + ks * 32);
            mma_tf32(acc[0][0], a0, b01);     mma_tf32(acc[1][0], a1, b01);
            mma_tf32(acc[0][1], a0, b01 + 2); mma_tf32(acc[1][1], a1, b01 + 2);
            mma_tf32(acc[0][2], a0, b23);     mma_tf32(acc[1][2], a1, b23);
            mma_tf32(acc[0][3], a0, b23 + 2); mma_tf32(acc[1][3], a1, b23 + 2);
        }
        st = (st == 2) ? 0 : st + 1;
        st2 = (st2 == 2) ? 0 : st2 + 1;
    }

#pragma unroll
    for (int mt = 0; mt < 2; mt++)
#pragma unroll
        for (int nt = 0; nt < 4; nt++)
#pragma unroll
            for (int p = 0; p < 4; p++) {
                int row = bm + wm * 32 + mt * 16 + (lane >> 2) + ((p & 2) ? 8 : 0);
                int col = bn + wn * 32 + nt * 8 + 2 * (lane & 3) + (p & 1);
                int b_ = row >> 8;
                int t_ = row & 255;
                int gate = col >> 10, within = col & 1023;
                int bnp = within >> 3, cwi = within & 7;
                g_G0p[(((size_t)t_ * NB + bnp) * 64 + b_) * 32 + gate * 8 + cwi] =
                    acc[mt][nt][p] + __ldg(&b0[col]);
            }
}

// ---------------- persistent merged recurrence (fp16 MMA) ----------------
__global__ void __launch_bounds__(512, 1) lstm_persist() {
    extern __shared__ float sm[];
    uint32_t sb = (uint32_t)__cvta_generic_to_shared(sm);
    const int tid = threadIdx.x, lane = tid & 31, warp = tid >> 5;
    const int wk = warp & 3, wn = (warp >> 2) & 1, wm = warp >> 3;
    const int bn = blockIdx.x;
    const int erow = tid >> 3, ecw = tid & 7;

    // A: 64 rows x 128 halves (256B) + 16B pad => 272B stride; 1024 cp16 / 512 thr = 2 each
    uint32_t dstA[2], srcA[2];
#pragma unroll
    for (int j = 0; j < 2; j++) {
        int c = j * 512 + tid;
        int row = c >> 4, kc = c & 15;
        dstA[j] = row * 272u + kc * 16u;
        srcA[j] = (uint32_t)(row * 2048 + kc * 16);   // bytes (row stride = 1024 halves)
    }
    // B: per set 32 cols x 272B; 512 cp16 = 1/thread
    uint32_t dstB, srcB;
    {
        int col = tid >> 4, kc = tid & 15;
        dstB = B_REGION + col * 272u + kc * 16u;
        srcB = (uint32_t)(col * 256 + kc * 16);       // bytes within [ii] slab
    }
    const size_t wbn = (size_t)bn * 65536u;           // bytes into packed fp16 W
    const char* W0base = (const char*)g_Wh0h + wbn;
    const char* W1base = (const char*)g_Wx1h + wbn;
    const char* W2base = (const char*)g_Wh1h + wbn;

    const uint32_t laneoffA = (wm * 32 + (lane & 15)) * 272u + (lane >> 4) * 16u;
    const uint32_t laneoffB = B_REGION
        + (wn * 16 + ((lane >> 4) << 3) + (lane & 7)) * 272u + ((lane >> 3) & 1) * 16u;

    auto issueB = [&](int st, int i) {
        const uint32_t stb = sb + st * STAGE_B;
        const int seg = i >> 3, ii = i & 7;
        const char* Wp = (seg ? W2base : W0base) + ii * 8192;
        cp16(stb + dstB, Wp + srcB);
        if (!seg) {
            const char* Wq = W1base + ii * 8192;
            cp16(stb + dstB + BSET_OFF, Wq + srcB);
        }
    };
    auto issueA = [&](int st, int i, const char* A0, const char* A1) {
        const uint32_t stb = sb + st * STAGE_B;
        const int seg = i >> 3, ii = i & 7;
        const char* Ap = (seg ? A1 : A0) + ii * 256;
#pragma unroll
        for (int j = 0; j < 2; j++) cp16(stb + dstA[j], Ap + srcA[j]);
    };
    auto g0pref = [&](int t) {
        const float* g0src = g_G0p + ((size_t)t * NB + bn) * 2048;
        cp16(sb + G0_OFF + tid * 16, g0src + tid * 4);
    };

    float c0r = 0.f, c1r = 0.f;
    unsigned tgt = 0;

    issueB(0, 0); issueB(1, 1); g0pref(0); CP_COMMIT();
    {
        const char* A0 = (const char*)g_h0h[0];
        const char* A1 = (const char*)g_h1h[1];
        issueA(0, 0, A0, A1); CP_COMMIT();
        issueA(1, 1, A0, A1); CP_COMMIT();
    }

    for (int s = 0; s <= 256; s++) {
        const char* A0 = (const char*)g_h0h[s & 1];
        const char* A1 = (const char*)g_h1h[(s + 1) & 1];

        float acc0[2][2][4], acc1[2][2][4];
#pragma unroll
        for (int n = 0; n < 2; n++)
#pragma unroll
            for (int m = 0; m < 2; m++)
#pragma unroll
                for (int p = 0; p < 4; p++) { acc0[n][m][p] = 0.f; acc1[n][m][p] = 0.f; }

        int st = 0, st2 = 2;
        for (int i = 0; i < 16; i++) {
            CP_WAIT1();
            __syncthreads();
            if (i + 2 < 16) { issueA(st2, i + 2, A0, A1); issueB(st2, i + 2); }
            CP_COMMIT();

            // warp's k window within stage: wk*32 halves = wk*64 bytes; 2 ksteps of k16 (32B)
            const uint32_t sA  = sb + st * STAGE_B + laneoffA + wk * 64;
            const uint32_t sB0 = sb + st * STAGE_B + laneoffB + wk * 64;
            const int seg = i >> 3;
#pragma unroll
            for (int ks = 0; ks < 2; ks++) {
                uint32_t a0[4], a1[4], b0[4];
                ldsm4(a0, sA + ks * 32);
                ldsm4(a1, sA + 16 * 272 + ks * 32);
                ldsm4(b0, sB0 + ks * 32);
                if (seg) {
                    mma_f16(acc1[0][0], a0, b0);     mma_f16(acc1[0][1], a1, b0);
                    mma_f16(acc1[1][0], a0, b0 + 2); mma_f16(acc1[1][1], a1, b0 + 2);
                } else {
                    uint32_t b1[4];
                    ldsm4(b1, sB0 + BSET_OFF + ks * 32);
                    mma_f16(acc0[0][0], a0, b0);     mma_f16(acc0[0][1], a1, b0);
                    mma_f16(acc0[1][0], a0, b0 + 2); mma_f16(acc0[1][1], a1, b0 + 2);
                    mma_f16(acc1[0][0], a0, b1);     mma_f16(acc1[0][1], a1, b1);
                    mma_f16(acc1[1][0], a0, b1 + 2); mma_f16(acc1[1][1], a1, b1 + 2);
                }
            }
            st = (st == 2) ? 0 : st + 1;
            st2 = (st2 == 2) ? 0 : st2 + 1;
        }
        CP_WAIT0();
        __syncthreads();

        // dump accumulators (aliases stage region: 8 x 64 x 36 floats = 73728B < 104448B)
        {
            const int row0 = wm * 32 + (lane >> 2);
            const int colb = wn * 16 + 2 * (lane & 3);
#pragma unroll
            for (int L = 0; L < 2; L++) {
                float (*acc)[2][4] = L ? acc1 : acc0;
                const int base = (wk * 2 + L) * 64;
#pragma unroll
                for (int nt = 0; nt < 2; nt++)
#pragma unroll
                    for (int mt = 0; mt < 2; mt++) {
                        const int r = base + row0 + mt * 16;
                        const int c = colb + nt * 8;
                        *(float2*)&sm[r * 36 + c] =
                            make_float2(acc[nt][mt][0], acc[nt][mt][1]);
                        *(float2*)&sm[(r + 8) * 36 + c] =
                            make_float2(acc[nt][mt][2], acc[nt][mt][3]);
                    }
            }
        }
        __syncthreads();

        // epilogue: one h element per thread per layer
        {
            float v0[4], v1[4];
#pragma unroll
            for (int g = 0; g < 4; g++) {
                float s0 = 0.f, s1 = 0.f;
#pragma unroll
                for (int k = 0; k < 4; k++) {
                    s0 += sm[((k * 2 + 0) * 64 + erow) * 36 + g * 8 + ecw];
                    s1 += sm[((k * 2 + 1) * 64 + erow) * 36 + g * 8 + ecw];
                }
                v0[g] = s0; v1[g] = s1;
            }
            const float* g0f = sm + (G0_OFF >> 2);
            const int hidx = erow * HH + bn * 8 + ecw;
            if (s < 256) {
                float iv = v0[0] + g0f[erow * 32 + ecw];
                float fv = v0[1] + g0f[erow * 32 + 8 + ecw];
                float gv = v0[2] + g0f[erow * 32 + 16 + ecw];
                float ov = v0[3] + g0f[erow * 32 + 24 + ecw];
                float cn = sigf(fv) * c0r + sigf(iv) * tanhf_(gv);
                c0r = cn;
                g_h0h[(s + 1) & 1][hidx] = __float2half_rn(sigf(ov) * tanhf_(cn));
            }
            if (s >= 1) {
                float iv = v1[0] + __ldg(&g_b1p[bn * 32 + ecw]);
                float fv = v1[1] + __ldg(&g_b1p[bn * 32 + 8 + ecw]);
                float gv = v1[2] + __ldg(&g_b1p[bn * 32 + 16 + ecw]);
                float ov = v1[3] + __ldg(&g_b1p[bn * 32 + 24 + ecw]);
                float cn = sigf(fv) * c1r + sigf(iv) * tanhf_(gv);
                c1r = cn;
                float h = sigf(ov) * tanhf_(cn);
                g_h1h[s & 1][hidx] = __float2half_rn(h);
                g_h1e[hidx] = h;
            }
        }
        __syncthreads();   // red-buffer reads done before prefetch overwrites stages 0/1

        // prefetch next superstep's weights + G0 (barrier-independent)
        if (s < 256) {
            issueB(0, 0); issueB(1, 1); g0pref(min(s + 1, 255));
        }
        CP_COMMIT();

        // grid barrier
        tgt += NB;
        if (tid == 0) {
            __threadfence();
            atomicAdd(&g_bar, 1u);
            while (*(volatile unsigned*)&g_bar < tgt) {}
            __threadfence();
        }
        __syncthreads();

        // A loads depend on the barrier
        if (s < 256) {
            const char* A0n = (const char*)g_h0h[(s + 1) & 1];
            const char* A1n = (const char*)g_h1h[s & 1];
            issueA(0, 0, A0n, A1n); CP_COMMIT();
            issueA(1, 1, A0n, A1n); CP_COMMIT();
        }
    }
}

__global__ void copy_out_kernel(float* __restrict__ out) {
    int i = blockIdx.x * blockDim.x + threadIdx.x;
    if (i < BB * HH) out[i] = g_h1e[i];
}

// ---------------- launch ----------------
extern "C" void kernel_launch(void* const* d_in, const int* in_sizes, int n_in,
                              void* d_out, int out_size) {
    const float* x   = (const float*)d_in[0];
    const float* Wx0 = (const float*)d_in[1];
    const float* Wh0 = (const float*)d_in[2];
    const float* b0  = (const float*)d_in[3];
    const float* Wx1 = (const float*)d_in[4];
    const float* Wh1 = (const float*)d_in[5];
    const float* b1  = (const float*)d_in[6];
    (void)in_sizes; (void)n_in; (void)out_size;

    cudaFuncSetAttribute(lstm_persist, cudaFuncAttributeMaxDynamicSharedMemorySize, SMEM_BYTES);
    cudaFuncSetAttribute(xgemm_kernel, cudaFuncAttributeMaxDynamicSharedMemorySize, XSMEM);

    convert_pack_kernel<<<4096, 256>>>(Wx0, Wh0, Wx1, Wh1, b1);
    init_kernel<<<256, 256>>>();

    dim3 grid_x(G4 / 64, (BB * TT) / 128);
    xgemm_kernel<<<grid_x, 256, XSMEM>>>(x, b0);

    lstm_persist<<<NB, 512, SMEM_BYTES>>>();

    copy_out_kernel<<<(BB * HH + 255) / 256, 256>>>((float*)d_out);
}

// round 9
// speedup vs baseline: 3.0424x; 1.2793x over previous
#include <cuda_runtime.h>
#include <cuda_fp16.h>
#include <cstdint>
#include <cstddef>

#define BB   64
#define TT   256
#define DD   1024
#define HH   1024
#define G4   4096
#define NB   128

// ---------------- device scratch ----------------
__device__ __align__(256) float  g_G0p[(size_t)TT * NB * 64 * 32]; // [t][bn][row64][gate8*4] fp32
__device__ __align__(256) float  g_Wx0p[DD * G4];    // tf32 col-major (xgemm)
__device__ __align__(256) __half g_Wh0h[HH * G4];    // fp16 swizzled tiles [bn][ii8][col32][kin128]
__device__ __align__(256) __half g_Wx1h[HH * G4];
__device__ __align__(256) __half g_Wh1h[HH * G4];
__device__ float  g_b1p[NB * 32];
__device__ __align__(256) __half g_h0h[2][BB * HH];  // fp16 swizzled k-tiles [ii8][row64][kin128]
__device__ __align__(256) __half g_h1h[2][BB * HH];
__device__ float  g_h1e[BB * HH];
__device__ unsigned g_bar;

// ---------------- smem layout (bytes) ----------------
// stage (32768): A tile 16384 | B0 8192 | B1 8192 ; 3 stages
#define STAGE_SZ  32768
#define G0_OFF    98304
#define MB_OFF    106496
#define SMEM_BYTES 118784   // > half of SM smem -> forces 1 block/SM

// ---------------- helpers ----------------
__device__ __forceinline__ uint32_t f2tf(float x) {
    uint32_t r; asm("cvt.rna.tf32.f32 %0, %1;" : "=r"(r) : "f"(x)); return r;
}
__device__ __forceinline__ void mma_tf32(float* d, const uint32_t* a, const uint32_t* b) {
    asm volatile(
        "mma.sync.aligned.m16n8k8.row.col.f32.tf32.tf32.f32 "
        "{%0,%1,%2,%3}, {%4,%5,%6,%7}, {%8,%9}, {%0,%1,%2,%3};"
        : "+f"(d[0]), "+f"(d[1]), "+f"(d[2]), "+f"(d[3])
        : "r"(a[0]), "r"(a[1]), "r"(a[2]), "r"(a[3]), "r"(b[0]), "r"(b[1]));
}
__device__ __forceinline__ void mma_f16(float* d, const uint32_t* a, const uint32_t* b) {
    asm volatile(
        "mma.sync.aligned.m16n8k16.row.col.f32.f16.f16.f32 "
        "{%0,%1,%2,%3}, {%4,%5,%6,%7}, {%8,%9}, {%0,%1,%2,%3};"
        : "+f"(d[0]), "+f"(d[1]), "+f"(d[2]), "+f"(d[3])
        : "r"(a[0]), "r"(a[1]), "r"(a[2]), "r"(a[3]), "r"(b[0]), "r"(b[1]));
}
__device__ __forceinline__ void ldsm4(uint32_t* r, uint32_t addr) {
    asm volatile("ldmatrix.sync.aligned.m8n8.x4.shared.b16 {%0,%1,%2,%3}, [%4];"
        : "=r"(r[0]), "=r"(r[1]), "=r"(r[2]), "=r"(r[3]) : "r"(addr));
}
__device__ __forceinline__ void cp16(uint32_t s, const void* g) {
    asm volatile("cp.async.cg.shared.global [%0], [%1], 16;" :: "r"(s), "l"(g));
}
#define CP_COMMIT() asm volatile("cp.async.commit_group;")
#define CP_WAIT1()  asm volatile("cp.async.wait_group 1;")

__device__ __forceinline__ void mbar_init(uint32_t a, uint32_t cnt) {
    asm volatile("mbarrier.init.shared.b64 [%0], %1;" :: "r"(a), "r"(cnt) : "memory");
}
__device__ __forceinline__ void mbar_expect(uint32_t a, uint32_t tx) {
    asm volatile("mbarrier.arrive.expect_tx.shared.b64 _, [%0], %1;" :: "r"(a), "r"(tx) : "memory");
}
__device__ __forceinline__ void bulkcp(uint32_t dst, const void* src, uint32_t sz, uint32_t mb) {
    asm volatile(
        "cp.async.bulk.shared::cluster.global.mbarrier::complete_tx::bytes [%0], [%1], %2, [%3];"
        :: "r"(dst), "l"(src), "r"(sz), "r"(mb) : "memory");
}
__device__ __forceinline__ void mbar_wait(uint32_t a, uint32_t par) {
    asm volatile(
        "{\n\t.reg .pred P;\n\tWAIT%=:\n\t"
        "mbarrier.try_wait.parity.acquire.cta.shared::cta.b64 P, [%0], %1;\n\t"
        "@!P bra WAIT%=;\n\t}"
        :: "r"(a), "r"(par) : "memory");
}

__device__ __forceinline__ float sigf(float x)   { return 1.f / (1.f + __expf(-x)); }
__device__ __forceinline__ float tanhf_(float x) { return 2.f / (1.f + __expf(-2.f * x)) - 1.f; }

// ---------------- convert + pack (weights swizzled fp16 tiles) ----------------
__global__ void convert_pack_kernel(const float* __restrict__ Wx0, const float* __restrict__ Wh0,
                                    const float* __restrict__ Wx1, const float* __restrict__ Wh1,
                                    const float* __restrict__ b1) {
    const int n1 = 1 << 22;
    const int stride = gridDim.x * blockDim.x;
    for (int idx = blockIdx.x * blockDim.x + threadIdx.x; idx < 4 * n1; idx += stride) {
        int w = idx >> 22;
        int d = idx & (n1 - 1);
        if (w == 0) {
            int k = d & 1023, col = d >> 10;
            g_Wx0p[d] = __uint_as_float(f2tf(Wx0[(size_t)k * G4 + col]));
        } else {
            int kin = d & 127, col = (d >> 7) & 31, ii = (d >> 12) & 7, bq = d >> 15;
            int gate = col >> 3, cw = col & 7;
            int k = ii * 128 + kin;
            int src = k * G4 + gate * HH + bq * 8 + cw;
            float v = (w == 1) ? Wh0[src] : (w == 2) ? Wx1[src] : Wh1[src];
            uint32_t off = (uint32_t)col * 256 + (uint32_t)kin * 2;
            uint32_t sw = off ^ ((off >> 4) & 0x70);
            __half* dst = (w == 1) ? g_Wh0h : (w == 2) ? g_Wx1h : g_Wh1h;
            dst[(size_t)(bq * 8 + ii) * 4096 + (sw >> 1)] = __float2half_rn(v);
        }
    }
    for (int i = blockIdx.x * blockDim.x + threadIdx.x; i < NB * 32; i += stride) {
        int bn = i >> 5, c = i & 31, gate = c >> 3, cw = c & 7;
        g_b1p[i] = b1[gate * HH + bn * 8 + cw];
    }
}

__global__ void init_kernel() {
    int i = blockIdx.x * blockDim.x + threadIdx.x;
    if (i < BB * HH) {
        g_h0h[0][i] = __float2half(0.f); g_h0h[1][i] = __float2half(0.f);
        g_h1h[0][i] = __float2half(0.f); g_h1h[1][i] = __float2half(0.f);
    }
    if (i == 0) g_bar = 0u;
}

// ---------------- precompute G0 = X @ Wx0 + b0 (tf32, unchanged) ----------------
#define XSTAGE 27648
#define XSMEM  (3 * XSTAGE)

__global__ void __launch_bounds__(256, 2) xgemm_kernel(const float* __restrict__ x,
                                                       const float* __restrict__ b0) {
    extern __shared__ float xsm[];
    uint32_t sb = (uint32_t)__cvta_generic_to_shared(xsm);
    const int tid = threadIdx.x, lane = tid & 31, warp = tid >> 5;
    const int wm = warp & 3, wn = warp >> 2;
    const int bm = blockIdx.y * 128;
    const int bn = blockIdx.x * 64;

    uint32_t dstA[4], srcA[4];
#pragma unroll
    for (int j = 0; j < 4; j++) {
        int c = j * 256 + tid, row = c >> 3, kc = c & 7;
        dstA[j] = row * 144u + kc * 16u;
        srcA[j] = (uint32_t)((bm + row) * DD + kc * 4) * 4u;
    }
    uint32_t dstB[2], srcB[2];
#pragma unroll
    for (int j = 0; j < 2; j++) {
        int c = j * 256 + tid, col = c >> 3, kc = c & 7;
        dstB[j] = 18432u + col * 144u + kc * 16u;
        srcB[j] = (uint32_t)((bn + col) * DD + kc * 4) * 4u;
    }
    const uint32_t laneoffA = ((wm * 32 + (lane & 15)) * 36u + (lane >> 4) * 4u) * 4u;
    const uint32_t laneoffB = 18432u + ((wn * 32 + ((lane >> 4) << 3) + (lane & 7)) * 36u
                                        + ((lane >> 3) & 1) * 4u) * 4u;

    auto issue = [&](int st, int k0) {
        const uint32_t stb = sb + st * XSTAGE;
        const char* xb = (const char*)x + (size_t)k0 * 4;
        const char* wb = (const char*)g_Wx0p + (size_t)k0 * 4;
#pragma unroll
        for (int j = 0; j < 4; j++) cp16(stb + dstA[j], xb + srcA[j]);
#pragma unroll
        for (int j = 0; j < 2; j++) cp16(stb + dstB[j], wb + srcB[j]);
    };

    float acc[2][4][4];
#pragma unroll
    for (int m = 0; m < 2; m++)
#pragma unroll
        for (int n = 0; n < 4; n++)
#pragma unroll
            for (int p = 0; p < 4; p++) acc[m][n][p] = 0.f;

    issue(0, 0); CP_COMMIT();
    issue(1, 32); CP_COMMIT();

    int st = 0, st2 = 2;
    for (int it = 0; it < 32; it++) {
        CP_WAIT1();
        __syncthreads();
        if (it + 2 < 32) issue(st2, (it + 2) * 32);
        CP_COMMIT();

        const uint32_t base = sb + st * XSTAGE;
#pragma unroll
        for (int ks = 0; ks < 4; ks++) {
            uint32_t a0[4], a1[4], b01[4], b23[4];
            ldsm4(a0, base + laneoffA + ks * 32);
            ldsm4(a1, base + laneoffA + 2304 + ks * 32);
            ldsm4(b01, base + laneoffB + ks * 32);
            ldsm4(b23, base + laneoffB + 2304 + ks * 32);
            mma_tf32(acc[0][0], a0, b01);     mma_tf32(acc[1][0], a1, b01);
            mma_tf32(acc[0][1], a0, b01 + 2); mma_tf32(acc[1][1], a1, b01 + 2);
            mma_tf32(acc[0][2], a0, b23);     mma_tf32(acc[1][2], a1, b23);
            mma_tf32(acc[0][3], a0, b23 + 2); mma_tf32(acc[1][3], a1, b23 + 2);
        }
        st = (st == 2) ? 0 : st + 1;
        st2 = (st2 == 2) ? 0 : st2 + 1;
    }

#pragma unroll
    for (int mt = 0; mt < 2; mt++)
#pragma unroll
        for (int nt = 0; nt < 4; nt++)
#pragma unroll
            for (int p = 0; p < 4; p++) {
                int row = bm + wm * 32 + mt * 16 + (lane >> 2) + ((p & 2) ? 8 : 0);
                int col = bn + wn * 32 + nt * 8 + 2 * (lane & 3) + (p & 1);
                int b_ = row >> 8;
                int t_ = row & 255;
                int gate = col >> 10, within = col & 1023;
                int bnp = within >> 3, cwi = within & 7;
                g_G0p[(((size_t)t_ * NB + bnp) * 64 + b_) * 32 + gate * 8 + cwi] =
                    acc[mt][nt][p] + __ldg(&b0[col]);
            }
}

// ---------------- persistent merged recurrence (bulk-copy producer) ----------------
__global__ void __launch_bounds__(512, 1) lstm_persist() {
    extern __shared__ float sm[];
    uint32_t sb = (uint32_t)__cvta_generic_to_shared(sm);
    const int tid = threadIdx.x, lane = tid & 31, warp = tid >> 5;
    const int wk = warp & 3, wn = (warp >> 2) & 1, wm = warp >> 3;
    const int bn = blockIdx.x;
    const int erow = tid >> 3, ecw = tid & 7;

    const uint32_t mb_full0 = sb + MB_OFF;
    const uint32_t mb_g0    = sb + MB_OFF + 24;
    if (tid == 0) {
        mbar_init(mb_full0,      2);
        mbar_init(mb_full0 + 8,  2);
        mbar_init(mb_full0 + 16, 2);
        mbar_init(mb_g0, 1);
    }
    __syncthreads();

    // ldmatrix lane offsets (swizzled, 256B row stride)
    const int rowA = wm * 32 + (lane & 15);
    const uint32_t kbA = (uint32_t)(lane >> 4) * 16 + (uint32_t)wk * 64;
    const int colB = wn * 16 + ((lane >> 4) << 3) + (lane & 7);
    const uint32_t kbB = (uint32_t)((lane >> 3) & 1) * 16 + (uint32_t)wk * 64;
    uint32_t laneA[2], laneB[2];
#pragma unroll
    for (int ks = 0; ks < 2; ks++) {
        laneA[ks] = (uint32_t)rowA * 256 + ((kbA + ks * 32) ^ (((uint32_t)rowA & 7) << 4));
        laneB[ks] = 16384u + (uint32_t)colB * 256 + ((kbB + ks * 32) ^ (((uint32_t)colB & 7) << 4));
    }

    const char* W0base = (const char*)g_Wh0h + (size_t)bn * 65536;
    const char* W1base = (const char*)g_Wx1h + (size_t)bn * 65536;
    const char* W2base = (const char*)g_Wh1h + (size_t)bn * 65536;

    auto fillB = [&](int st, int fi) {
        const uint32_t mb = mb_full0 + st * 8;
        const int seg = fi >> 3, ii = fi & 7;
        const uint32_t d = sb + st * STAGE_SZ + 16384;
        if (seg) {
            mbar_expect(mb, 8192);
            bulkcp(d, W2base + ii * 8192, 8192, mb);
        } else {
            mbar_expect(mb, 16384);
            bulkcp(d,        W0base + ii * 8192, 8192, mb);
            bulkcp(d + 8192, W1base + ii * 8192, 8192, mb);
        }
    };
    auto fillA = [&](int st, int fi, const char* A0, const char* A1) {
        const uint32_t mb = mb_full0 + st * 8;
        const int seg = fi >> 3, ii = fi & 7;
        const char* src = (seg ? A1 : A0) + ii * 16384;
        const uint32_t d = sb + st * STAGE_SZ;
        mbar_expect(mb, 16384);
        bulkcp(d,        src,        8192, mb);
        bulkcp(d + 8192, src + 8192, 8192, mb);
    };
    auto fillG0 = [&](int t) {
        mbar_expect(mb_g0, 8192);
        bulkcp(sb + G0_OFF, (const char*)g_G0p + ((size_t)t * NB + bn) * 8192, 8192, mb_g0);
    };

    // epilogue h-store swizzled address
    const int iiH = bn >> 4;
    const int kinH = (bn & 15) * 8 + ecw;
    const uint32_t offH = (uint32_t)erow * 256 + (uint32_t)kinH * 2;
    const uint32_t swH = offH ^ ((offH >> 4) & 0x70);
    const int physH = iiH * 8192 + (int)(swH >> 1);

    float c0r = 0.f, c1r = 0.f;
    unsigned tgt = 0;

    // initial fills for superstep 0 (iters 0,1)
    if (tid == 0) {
        const char* A0i = (const char*)g_h0h[0];
        const char* A1i = (const char*)g_h1h[1];
        fillB(0, 0); fillB(1, 1); fillG0(0);
        fillA(0, 0, A0i, A1i); fillA(1, 1, A0i, A1i);
    }

    for (int s = 0; s <= 256; s++) {
        const char* A0 = (const char*)g_h0h[s & 1];
        const char* A1 = (const char*)g_h1h[(s + 1) & 1];

        float acc0[2][2][4], acc1[2][2][4];
#pragma unroll
        for (int n = 0; n < 2; n++)
#pragma unroll
            for (int m = 0; m < 2; m++)
#pragma unroll
                for (int p = 0; p < 4; p++) { acc0[n][m][p] = 0.f; acc1[n][m][p] = 0.f; }

#pragma unroll
        for (int i = 0; i < 16; i++) {
            const int stc = i % 3, j = i / 3, seg = i >> 3;
            const uint32_t par = (stc == 0) ? (uint32_t)(j & 1) : (uint32_t)((s + j) & 1);
            mbar_wait(mb_full0 + stc * 8, par);
            __syncthreads();
            if (i + 2 < 16 && tid == 0) {
                const int st2 = (i + 2) % 3;
                fillA(st2, i + 2, A0, A1);
                fillB(st2, i + 2);
            }
            const uint32_t stgb = sb + stc * STAGE_SZ;
#pragma unroll
            for (int ks = 0; ks < 2; ks++) {
                uint32_t a0[4], a1[4], b0[4];
                ldsm4(a0, stgb + laneA[ks]);
                ldsm4(a1, stgb + laneA[ks] + 4096);
                ldsm4(b0, stgb + laneB[ks]);
                if (seg) {
                    mma_f16(acc1[0][0], a0, b0);     mma_f16(acc1[0][1], a1, b0);
                    mma_f16(acc1[1][0], a0, b0 + 2); mma_f16(acc1[1][1], a1, b0 + 2);
                } else {
                    uint32_t b1[4];
                    ldsm4(b1, stgb + laneB[ks] + 8192);
                    mma_f16(acc0[0][0], a0, b0);     mma_f16(acc0[0][1], a1, b0);
                    mma_f16(acc0[1][0], a0, b0 + 2); mma_f16(acc0[1][1], a1, b0 + 2);
                    mma_f16(acc1[0][0], a0, b1);     mma_f16(acc1[0][1], a1, b1);
                    mma_f16(acc1[1][0], a0, b1 + 2); mma_f16(acc1[1][1], a1, b1 + 2);
                }
            }
        }
        __syncthreads();

        // dump accumulators (aliases stage region: 73728B < 98304B)
        {
            const int row0 = wm * 32 + (lane >> 2);
            const int colb = wn * 16 + 2 * (lane & 3);
#pragma unroll
            for (int L = 0; L < 2; L++) {
                float (*acc)[2][4] = L ? acc1 : acc0;
                const int base = (wk * 2 + L) * 64;
#pragma unroll
                for (int nt = 0; nt < 2; nt++)
#pragma unroll
                    for (int mt = 0; mt < 2; mt++) {
                        const int r = base + row0 + mt * 16;
                        const int c = colb + nt * 8;
                        *(float2*)&sm[r * 36 + c] =
                            make_float2(acc[nt][mt][0], acc[nt][mt][1]);
                        *(float2*)&sm[(r + 8) * 36 + c] =
                            make_float2(acc[nt][mt][2], acc[nt][mt][3]);
                    }
            }
        }
        __syncthreads();

        if (s < 256) mbar_wait(mb_g0, (uint32_t)(s & 1));

        // epilogue: one h element per thread per layer
        {
            float v0[4], v1[4];
#pragma unroll
            for (int g = 0; g < 4; g++) {
                float s0 = 0.f, s1 = 0.f;
#pragma unroll
                for (int k = 0; k < 4; k++) {
                    s0 += sm[((k * 2 + 0) * 64 + erow) * 36 + g * 8 + ecw];
                    s1 += sm[((k * 2 + 1) * 64 + erow) * 36 + g * 8 + ecw];
                }
                v0[g] = s0; v1[g] = s1;
            }
            const float* g0f = sm + (G0_OFF >> 2);
            if (s < 256) {
                float iv = v0[0] + g0f[erow * 32 + ecw];
                float fv = v0[1] + g0f[erow * 32 + 8 + ecw];
                float gv = v0[2] + g0f[erow * 32 + 16 + ecw];
                float ov = v0[3] + g0f[erow * 32 + 24 + ecw];
                float cn = sigf(fv) * c0r + sigf(iv) * tanhf_(gv);
                c0r = cn;
                g_h0h[(s + 1) & 1][physH] = __float2half_rn(sigf(ov) * tanhf_(cn));
            }
            if (s >= 1) {
                float iv = v1[0] + __ldg(&g_b1p[bn * 32 + ecw]);
                float fv = v1[1] + __ldg(&g_b1p[bn * 32 + 8 + ecw]);
                float gv = v1[2] + __ldg(&g_b1p[bn * 32 + 16 + ecw]);
                float ov = v1[3] + __ldg(&g_b1p[bn * 32 + 24 + ecw]);
                float cn = sigf(fv) * c1r + sigf(iv) * tanhf_(gv);
                c1r = cn;
                float h = sigf(ov) * tanhf_(cn);
                g_h1h[s & 1][physH] = __float2half_rn(h);
                g_h1e[erow * HH + bn * 8 + ecw] = h;
            }
        }
        __syncthreads();   // epilogue reads done before prefetch overwrites dump/stage area

        // prefetch next superstep's weights + G0 (barrier-independent)
        if (tid == 0 && s < 256) {
            fillB(0, 0); fillB(1, 1);
            if (s < 255) fillG0(s + 1);
        }

        // grid barrier
        tgt += NB;
        if (tid == 0) {
            __threadfence();
            atomicAdd(&g_bar, 1u);
            while (*(volatile unsigned*)&g_bar < tgt) {}
            __threadfence();
        }
        __syncthreads();

        // A fills depend on the barrier
        if (tid == 0 && s < 256) {
            const char* A0n = (const char*)g_h0h[(s + 1) & 1];
            const char* A1n = (const char*)g_h1h[s & 1];
            fillA(0, 0, A0n, A1n);
            fillA(1, 1, A0n, A1n);
        }
    }
}

__global__ void copy_out_kernel(float* __restrict__ out) {
    int i = blockIdx.x * blockDim.x + threadIdx.x;
    if (i < BB * HH) out[i] = g_h1e[i];
}

// ---------------- launch ----------------
extern "C" void kernel_launch(void* const* d_in, const int* in_sizes, int n_in,
                              void* d_out, int out_size) {
    const float* x   = (const float*)d_in[0];
    const float* Wx0 = (const float*)d_in[1];
    const float* Wh0 = (const float*)d_in[2];
    const float* b0  = (const float*)d_in[3];
    const float* Wx1 = (const float*)d_in[4];
    const float* Wh1 = (const float*)d_in[5];
    const float* b1  = (const float*)d_in[6];
    (void)in_sizes; (void)n_in; (void)out_size;

    cudaFuncSetAttribute(lstm_persist, cudaFuncAttributeMaxDynamicSharedMemorySize, SMEM_BYTES);
    cudaFuncSetAttribute(xgemm_kernel, cudaFuncAttributeMaxDynamicSharedMemorySize, XSMEM);

    convert_pack_kernel<<<4096, 256>>>(Wx0, Wh0, Wx1, Wh1, b1);
    init_kernel<<<256, 256>>>();

    dim3 grid_x(G4 / 64, (BB * TT) / 128);
    xgemm_kernel<<<grid_x, 256, XSMEM>>>(x, b0);

    lstm_persist<<<NB, 512, SMEM_BYTES>>>();

    copy_out_kernel<<<(BB * HH + 255) / 256, 256>>>((float*)d_out);
}

// round 11
// speedup vs baseline: 3.2156x; 1.0569x over previous
#include <cuda_runtime.h>
#include <cuda_fp16.h>
#include <cstdint>
#include <cstddef>

#define BB   64
#define TT   256
#define DD   1024
#define HH   1024
#define G4   4096
#define NB   128

// ---------------- device scratch ----------------
__device__ __align__(256) float  g_G0p[(size_t)TT * NB * 64 * 32]; // [t][bn][row64][gate8*4] fp32
__device__ __align__(256) __half g_Xh[(size_t)BB * TT * DD];       // fp16 X, row-major
__device__ __align__(256) __half g_Wx0h[DD * G4];                  // fp16 col-major [col][k]
__device__ __align__(256) __half g_Wh0h[HH * G4];    // fp16 swizzled tiles [bn][ii8][col32][kin128]
__device__ __align__(256) __half g_Wx1h[HH * G4];
__device__ __align__(256) __half g_Wh1h[HH * G4];
__device__ float  g_b1p[NB * 32];
__device__ __align__(256) __half g_h0h[2][BB * HH];  // fp16 swizzled k-tiles [ii8][row64][kin128]
__device__ __align__(256) __half g_h1h[2][BB * HH];
__device__ float  g_h1e[BB * HH];
__device__ unsigned g_bar;

// ---------------- smem layout (bytes) ----------------
// stage (32768): A tile 16384 | B0 8192 | B1 8192 ; 5 stages
#define STAGE_SZ  32768
#define NSTG      5
#define G0_OFF    163840
#define MB_OFF    172032
#define SMEM_BYTES 172544

// ---------------- helpers ----------------
__device__ __forceinline__ void mma_f16(float* d, const uint32_t* a, const uint32_t* b) {
    asm volatile(
        "mma.sync.aligned.m16n8k16.row.col.f32.f16.f16.f32 "
        "{%0,%1,%2,%3}, {%4,%5,%6,%7}, {%8,%9}, {%0,%1,%2,%3};"
        : "+f"(d[0]), "+f"(d[1]), "+f"(d[2]), "+f"(d[3])
        : "r"(a[0]), "r"(a[1]), "r"(a[2]), "r"(a[3]), "r"(b[0]), "r"(b[1]));
}
__device__ __forceinline__ void ldsm4(uint32_t* r, uint32_t addr) {
    asm volatile("ldmatrix.sync.aligned.m8n8.x4.shared.b16 {%0,%1,%2,%3}, [%4];"
        : "=r"(r[0]), "=r"(r[1]), "=r"(r[2]), "=r"(r[3]) : "r"(addr));
}
__device__ __forceinline__ void cp16(uint32_t s, const void* g) {
    asm volatile("cp.async.cg.shared.global [%0], [%1], 16;" :: "r"(s), "l"(g));
}
#define CP_COMMIT() asm volatile("cp.async.commit_group;")
#define CP_WAIT1()  asm volatile("cp.async.wait_group 1;")

__device__ __forceinline__ void mbar_init(uint32_t a, uint32_t cnt) {
    asm volatile("mbarrier.init.shared.b64 [%0], %1;" :: "r"(a), "r"(cnt) : "memory");
}
__device__ __forceinline__ void mbar_expect(uint32_t a, uint32_t tx) {
    asm volatile("mbarrier.arrive.expect_tx.shared.b64 _, [%0], %1;" :: "r"(a), "r"(tx) : "memory");
}
__device__ __forceinline__ void bulkcp(uint32_t dst, const void* src, uint32_t sz, uint32_t mb) {
    asm volatile(
        "cp.async.bulk.shared::cluster.global.mbarrier::complete_tx::bytes [%0], [%1], %2, [%3];"
        :: "r"(dst), "l"(src), "r"(sz), "r"(mb) : "memory");
}
__device__ __forceinline__ void mbar_wait(uint32_t a, uint32_t par) {
    asm volatile(
        "{\n\t.reg .pred P;\n\tWAIT%=:\n\t"
        "mbarrier.try_wait.parity.acquire.cta.shared::cta.b64 P, [%0], %1;\n\t"
        "@!P bra WAIT%=;\n\t}"
        :: "r"(a), "r"(par) : "memory");
}

__device__ __forceinline__ float sigf(float x)   { return 1.f / (1.f + __expf(-x)); }
__device__ __forceinline__ float tanhf_(float x) { return 2.f / (1.f + __expf(-2.f * x)) - 1.f; }

// ---------------- convert + pack ----------------
__global__ void convert_pack_kernel(const float* __restrict__ x,
                                    const float* __restrict__ Wx0, const float* __restrict__ Wh0,
                                    const float* __restrict__ Wx1, const float* __restrict__ Wh1,
                                    const float* __restrict__ b1) {
    const int n1 = 1 << 22;
    const int stride = gridDim.x * blockDim.x;
    for (int idx = blockIdx.x * blockDim.x + threadIdx.x; idx < 4 * n1; idx += stride) {
        int w = idx >> 22;
        int d = idx & (n1 - 1);
        if (w == 0) {
            int k = d & 1023, col = d >> 10;
            g_Wx0h[d] = __float2half_rn(Wx0[(size_t)k * G4 + col]);  // col-major
        } else {
            int kin = d & 127, col = (d >> 7) & 31, ii = (d >> 12) & 7, bq = d >> 15;
            int gate = col >> 3, cw = col & 7;
            int k = ii * 128 + kin;
            int src = k * G4 + gate * HH + bq * 8 + cw;
            float v = (w == 1) ? Wh0[src] : (w == 2) ? Wx1[src] : Wh1[src];
            uint32_t off = (uint32_t)col * 256 + (uint32_t)kin * 2;
            uint32_t sw = off ^ ((off >> 4) & 0x70);
            __half* dst = (w == 1) ? g_Wh0h : (w == 2) ? g_Wx1h : g_Wh1h;
            dst[(size_t)(bq * 8 + ii) * 4096 + (sw >> 1)] = __float2half_rn(v);
        }
    }
    for (size_t i = blockIdx.x * blockDim.x + threadIdx.x; i < (size_t)BB * TT * DD; i += stride)
        g_Xh[i] = __float2half_rn(x[i]);
    for (int i = blockIdx.x * blockDim.x + threadIdx.x; i < NB * 32; i += stride) {
        int bn = i >> 5, c = i & 31, gate = c >> 3, cw = c & 7;
        g_b1p[i] = b1[gate * HH + bn * 8 + cw];
    }
}

__global__ void init_kernel() {
    int i = blockIdx.x * blockDim.x + threadIdx.x;
    if (i < BB * HH) {
        g_h0h[0][i] = __float2half(0.f); g_h0h[1][i] = __float2half(0.f);
        g_h1h[0][i] = __float2half(0.f); g_h1h[1][i] = __float2half(0.f);
    }
    if (i == 0) g_bar = 0u;
}

// ---------------- precompute G0 = X @ Wx0 + b0 (fp16 HMMA) ----------------
// BM=128, BN=64, BK=32, 256 thr (wm 0-3 x 32 rows, wn 0-1 x 32 cols), 3-stage cp.async
#define XSTAGE 15360   // A: 128 rows x 80B (10240) + B: 64 cols x 80B (5120)
#define XSMEM  (3 * XSTAGE)

__global__ void __launch_bounds__(256, 2) xgemm_kernel(const float* __restrict__ b0) {
    extern __shared__ float xsm[];
    uint32_t sb = (uint32_t)__cvta_generic_to_shared(xsm);
    const int tid = threadIdx.x, lane = tid & 31, warp = tid >> 5;
    const int wm = warp & 3, wn = warp >> 2;
    const int bm = blockIdx.y * 128;
    const int bn = blockIdx.x * 64;

    uint32_t dstA[2], srcA[2];
#pragma unroll
    for (int j = 0; j < 2; j++) {
        int c = j * 256 + tid, row = c >> 2, kc = c & 3;
        dstA[j] = row * 80u + kc * 16u;
        srcA[j] = (uint32_t)((bm + row) * 2048 + kc * 16);   // bytes, fp16 row stride 2048B
    }
    uint32_t dstB, srcB;
    {
        int col = tid >> 2, kc = tid & 3;
        dstB = 10240u + col * 80u + kc * 16u;
        srcB = (uint32_t)((bn + col) * 2048 + kc * 16);
    }
    const uint32_t laneoffA = (wm * 32 + (lane & 15)) * 80u + (lane >> 4) * 16u;
    const uint32_t laneoffB = 10240u + (wn * 32 + ((lane >> 4) << 3) + (lane & 7)) * 80u
                              + ((lane >> 3) & 1) * 16u;

    auto issue = [&](int st, int k0) {
        const uint32_t stb = sb + st * XSTAGE;
        const char* xb = (const char*)g_Xh + (size_t)k0 * 2;
        const char* wb = (const char*)g_Wx0h + (size_t)k0 * 2;
#pragma unroll
        for (int j = 0; j < 2; j++) cp16(stb + dstA[j], xb + srcA[j]);
        cp16(stb + dstB, wb + srcB);
    };

    float acc[2][4][4];
#pragma unroll
    for (int m = 0; m < 2; m++)
#pragma unroll
        for (int n = 0; n < 4; n++)
#pragma unroll
            for (int p = 0; p < 4; p++) acc[m][n][p] = 0.f;

    issue(0, 0); CP_COMMIT();
    issue(1, 32); CP_COMMIT();

    int st = 0, st2 = 2;
    for (int it = 0; it < 32; it++) {
        CP_WAIT1();
        __syncthreads();
        if (it + 2 < 32) issue(st2, (it + 2) * 32);
        CP_COMMIT();

        const uint32_t base = sb + st * XSTAGE;
#pragma unroll
        for (int ks = 0; ks < 2; ks++) {
            uint32_t a0[4], a1[4], b01[4], b23[4];
            ldsm4(a0, base + laneoffA + ks * 32);
            ldsm4(a1, base + laneoffA + 1280 + ks * 32);
            ldsm4(b01, base + laneoffB + ks * 32);
            ldsm4(b23, base + laneoffB + 1280 + ks * 32);
            mma_f16(acc[0][0], a0, b01);     mma_f16(acc[1][0], a1, b01);
            mma_f16(acc[0][1], a0, b01 + 2); mma_f16(acc[1][1], a1, b01 + 2);
            mma_f16(acc[0][2], a0, b23);     mma_f16(acc[1][2], a1, b23);
            mma_f16(acc[0][3], a0, b23 + 2); mma_f16(acc[1][3], a1, b23 + 2);
        }
        st = (st == 2) ? 0 : st + 1;
        st2 = (st2 == 2) ? 0 : st2 + 1;
    }

#pragma unroll
    for (int mt = 0; mt < 2; mt++)
#pragma unroll
        for (int nt = 0; nt < 4; nt++)
#pragma unroll
            for (int p = 0; p < 4; p++) {
                int row = bm + wm * 32 + mt * 16 + (lane >> 2) + ((p & 2) ? 8 : 0);
                int col = bn + wn * 32 + nt * 8 + 2 * (lane & 3) + (p & 1);
                int b_ = row >> 8;
                int t_ = row & 255;
                int gate = col >> 10, within = col & 1023;
                int bnp = within >> 3, cwi = within & 7;
                g_G0p[(((size_t)t_ * NB + bnp) * 64 + b_) * 32 + gate * 8 + cwi] =
                    acc[mt][nt][p] + __ldg(&b0[col]);
            }
}

// ---------------- persistent merged recurrence (wk8 x wm2, 5-stage bulk pipeline) ----------------
__global__ void __launch_bounds__(512, 1) lstm_persist() {
    extern __shared__ float sm[];
    uint32_t sb = (uint32_t)__cvta_generic_to_shared(sm);
    const int tid = threadIdx.x, lane = tid & 31, warp = tid >> 5;
    const int wk = warp & 7, wm = warp >> 3;
    const int bn = blockIdx.x;
    const int erow = tid >> 3, ecw = tid & 7;

    const uint32_t mb0   = sb + MB_OFF;
    const uint32_t mb_g0 = sb + MB_OFF + NSTG * 8;
    if (tid == 0) {
#pragma unroll
        for (int i = 0; i < NSTG; i++) mbar_init(mb0 + i * 8, 2);
        mbar_init(mb_g0, 1);
    }
    __syncthreads();

    // ldmatrix lane offsets (swizzled 128B pattern, 256B row stride, k-window = wk*32 bytes)
    const uint32_t kbA = (uint32_t)wk * 32 + (uint32_t)(lane >> 4) * 16;
    const uint32_t laneA = (uint32_t)(wm * 32 + (lane & 15)) * 256
                           + (kbA ^ (((uint32_t)lane & 7) << 4));
    const uint32_t kbB = (uint32_t)wk * 32 + (uint32_t)((lane >> 3) & 1) * 16;
    const uint32_t laneB = 16384u + (uint32_t)(((lane >> 4) << 3) + (lane & 7)) * 256
                           + (kbB ^ (((uint32_t)lane & 7) << 4));

    const char* W0base = (const char*)g_Wh0h + (size_t)bn * 65536;
    const char* W1base = (const char*)g_Wx1h + (size_t)bn * 65536;
    const char* W2base = (const char*)g_Wh1h + (size_t)bn * 65536;

    auto fillB = [&](int st, int fi) {
        const uint32_t mb = mb0 + st * 8;
        const int seg = fi >> 3, ii = fi & 7;
        const uint32_t d = sb + st * STAGE_SZ + 16384;
        if (seg) {
            mbar_expect(mb, 8192);
            bulkcp(d, W2base + ii * 8192, 8192, mb);
        } else {
            mbar_expect(mb, 16384);
            bulkcp(d,        W0base + ii * 8192, 8192, mb);
            bulkcp(d + 8192, W1base + ii * 8192, 8192, mb);
        }
    };
    auto fillA = [&](int st, int fi, const char* A0, const char* A1) {
        const uint32_t mb = mb0 + st * 8;
        const int seg = fi >> 3, ii = fi & 7;
        const char* src = (seg ? A1 : A0) + ii * 16384;
        const uint32_t d = sb + st * STAGE_SZ;
        mbar_expect(mb, 16384);
        bulkcp(d,        src,        8192, mb);
        bulkcp(d + 8192, src + 8192, 8192, mb);
    };
    auto fillG0 = [&](int t) {
        mbar_expect(mb_g0, 8192);
        bulkcp(sb + G0_OFF, (const char*)g_G0p + ((size_t)t * NB + bn) * 8192, 8192, mb_g0);
    };

    // epilogue h-store swizzled address
    const int iiH = bn >> 4;
    const int kinH = (bn & 15) * 8 + ecw;
    const uint32_t offH = (uint32_t)erow * 256 + (uint32_t)kinH * 2;
    const uint32_t swH = offH ^ ((offH >> 4) & 0x70);
    const int physH = iiH * 8192 + (int)(swH >> 1);

    float c0r = 0.f, c1r = 0.f;
    unsigned tgt = 0;
    unsigned pb = 0;   // per-stage phase bits

    // initial fills: stages 0-3 (iters 0-3) + G0
    if (tid == 0) {
        const char* A0i = (const char*)g_h0h[0];
        const char* A1i = (const char*)g_h1h[1];
        fillG0(0);
#pragma unroll
        for (int j = 0; j < 4; j++) { fillA(j, j, A0i, A1i); fillB(j, j); }
    }

    for (int s = 0; s <= 256; s++) {
        const char* A0 = (const char*)g_h0h[s & 1];
        const char* A1 = (const char*)g_h1h[(s + 1) & 1];

        float acc0[2][4][4], acc1[2][4][4];
#pragma unroll
        for (int m = 0; m < 2; m++)
#pragma unroll
            for (int n = 0; n < 4; n++)
#pragma unroll
                for (int p = 0; p < 4; p++) { acc0[m][n][p] = 0.f; acc1[m][n][p] = 0.f; }

        int stc = 0, stf = 4;
#pragma unroll
        for (int i = 0; i < 16; i++) {
            mbar_wait(mb0 + stc * 8, (pb >> stc) & 1);
            pb ^= (1u << stc);
            __syncthreads();
            if (i + 4 < 16 && tid == 0) {
                fillA(stf, i + 4, A0, A1);
                fillB(stf, i + 4);
            }
            const uint32_t stgb = sb + stc * STAGE_SZ;
            const int seg = i >> 3;
            uint32_t a0[4], a1[4], b0[4], b1r[4];
            ldsm4(a0, stgb + laneA);
            ldsm4(a1, stgb + laneA + 4096);
            ldsm4(b0, stgb + laneB);
            ldsm4(b1r, stgb + laneB + 4096);
            if (seg) {
                mma_f16(acc1[0][0], a0, b0);      mma_f16(acc1[1][0], a1, b0);
                mma_f16(acc1[0][1], a0, b0 + 2);  mma_f16(acc1[1][1], a1, b0 + 2);
                mma_f16(acc1[0][2], a0, b1r);     mma_f16(acc1[1][2], a1, b1r);
                mma_f16(acc1[0][3], a0, b1r + 2); mma_f16(acc1[1][3], a1, b1r + 2);
            } else {
                uint32_t c0[4], c1v[4];
                ldsm4(c0, stgb + laneB + 8192);
                ldsm4(c1v, stgb + laneB + 12288);
                mma_f16(acc0[0][0], a0, b0);      mma_f16(acc0[1][0], a1, b0);
                mma_f16(acc0[0][1], a0, b0 + 2);  mma_f16(acc0[1][1], a1, b0 + 2);
                mma_f16(acc0[0][2], a0, b1r);     mma_f16(acc0[1][2], a1, b1r);
                mma_f16(acc0[0][3], a0, b1r + 2); mma_f16(acc0[1][3], a1, b1r + 2);
                mma_f16(acc1[0][0], a0, c0);      mma_f16(acc1[1][0], a1, c0);
                mma_f16(acc1[0][1], a0, c0 + 2);  mma_f16(acc1[1][1], a1, c0 + 2);
                mma_f16(acc1[0][2], a0, c1v);     mma_f16(acc1[1][2], a1, c1v);
                mma_f16(acc1[0][3], a0, c1v + 2); mma_f16(acc1[1][3], a1, c1v + 2);
            }
            stc = (stc == NSTG - 1) ? 0 : stc + 1;
            stf = (stf == NSTG - 1) ? 0 : stf + 1;
        }
        __syncthreads();

        // dump accumulators: [L2][wk8][row64][36] floats (147456B, aliases stage region)
        {
            const int row0 = wm * 32 + (lane >> 2);
            const int colb = 2 * (lane & 3);
#pragma unroll
            for (int L = 0; L < 2; L++) {
                float (*acc)[4][4] = L ? acc1 : acc0;
                const int base = (L * 8 + wk) * 64;
#pragma unroll
                for (int mt = 0; mt < 2; mt++)
#pragma unroll
                    for (int nt = 0; nt < 4; nt++) {
                        const int r = base + row0 + mt * 16;
                        const int c = nt * 8 + colb;
                        *(float2*)&sm[r * 36 + c] =
                            make_float2(acc[mt][nt][0], acc[mt][nt][1]);
                        *(float2*)&sm[(r + 8) * 36 + c] =
                            make_float2(acc[mt][nt][2], acc[mt][nt][3]);
                    }
            }
        }
        __syncthreads();

        if (s < 256) mbar_wait(mb_g0, (uint32_t)(s & 1));

        // epilogue: one h element per thread per layer; 8-way k reduction
        {
            float v0[4], v1[4];
#pragma unroll
            for (int g = 0; g < 4; g++) {
                float s0 = 0.f, s1 = 0.f;
#pragma unroll
                for (int k = 0; k < 8; k++) {
                    s0 += sm[((0 * 8 + k) * 64 + erow) * 36 + g * 8 + ecw];
                    s1 += sm[((1 * 8 + k) * 64 + erow) * 36 + g * 8 + ecw];
                }
                v0[g] = s0; v1[g] = s1;
            }
            const float* g0f = sm + (G0_OFF >> 2);
            if (s < 256) {
                float iv = v0[0] + g0f[erow * 32 + ecw];
                float fv = v0[1] + g0f[erow * 32 + 8 + ecw];
                float gv = v0[2] + g0f[erow * 32 + 16 + ecw];
                float ov = v0[3] + g0f[erow * 32 + 24 + ecw];
                float cn = sigf(fv) * c0r + sigf(iv) * tanhf_(gv);
                c0r = cn;
                g_h0h[(s + 1) & 1][physH] = __float2half_rn(sigf(ov) * tanhf_(cn));
            }
            if (s >= 1) {
                float iv = v1[0] + __ldg(&g_b1p[bn * 32 + ecw]);
                float fv = v1[1] + __ldg(&g_b1p[bn * 32 + 8 + ecw]);
                float gv = v1[2] + __ldg(&g_b1p[bn * 32 + 16 + ecw]);
                float ov = v1[3] + __ldg(&g_b1p[bn * 32 + 24 + ecw]);
                float cn = sigf(fv) * c1r + sigf(iv) * tanhf_(gv);
                c1r = cn;
                float h = sigf(ov) * tanhf_(cn);
                g_h1h[s & 1][physH] = __float2half_rn(h);
                g_h1e[erow * HH + bn * 8 + ecw] = h;
            }
        }
        __syncthreads();   // epilogue reads done before prefetch overwrites dump/stage area

        // prefetch next superstep's weights (stages 0-3) + G0 (barrier-independent)
        if (tid == 0 && s < 256) {
#pragma unroll
            for (int j = 0; j < 4; j++) fillB(j, j);
            if (s < 255) fillG0(s + 1);
        }

        // grid barrier
        tgt += NB;
        if (tid == 0) {
            __threadfence();
            atomicAdd(&g_bar, 1u);
            while (*(volatile unsigned*)&g_bar < tgt) {}
            __threadfence();
        }
        __syncthreads();

        // A fills depend on the barrier
        if (tid == 0 && s < 256) {
            const char* A0n = (const char*)g_h0h[(s + 1) & 1];
            const char* A1n = (const char*)g_h1h[s & 1];
#pragma unroll
            for (int j = 0; j < 4; j++) fillA(j, j, A0n, A1n);
        }
    }
}

__global__ void copy_out_kernel(float* __restrict__ out) {
    int i = blockIdx.x * blockDim.x + threadIdx.x;
    if (i < BB * HH) out[i] = g_h1e[i];
}

// ---------------- launch ----------------
extern "C" void kernel_launch(void* const* d_in, const int* in_sizes, int n_in,
                              void* d_out, int out_size) {
    const float* x   = (const float*)d_in[0];
    const float* Wx0 = (const float*)d_in[1];
    const float* Wh0 = (const float*)d_in[2];
    const float* b0  = (const float*)d_in[3];
    const float* Wx1 = (const float*)d_in[4];
    const float* Wh1 = (const float*)d_in[5];
    const float* b1  = (const float*)d_in[6];
    (void)in_sizes; (void)n_in; (void)out_size;

    cudaFuncSetAttribute(lstm_persist, cudaFuncAttributeMaxDynamicSharedMemorySize, SMEM_BYTES);
    cudaFuncSetAttribute(xgemm_kernel, cudaFuncAttributeMaxDynamicSharedMemorySize, XSMEM);

    convert_pack_kernel<<<4096, 256>>>(x, Wx0, Wh0, Wx1, Wh1, b1);
    init_kernel<<<256, 256>>>();

    dim3 grid_x(G4 / 64, (BB * TT) / 128);
    xgemm_kernel<<<grid_x, 256, XSMEM>>>(b0);

    lstm_persist<<<NB, 512, SMEM_BYTES>>>();

    copy_out_kernel<<<(BB * HH + 255) / 256, 256>>>((float*)d_out);
}